// round 4
// baseline (speedup 1.0000x reference)
#include <cuda_runtime.h>
#include <cuda_bf16.h>
#include <cstdint>
#include <math_constants.h>

static constexpr int Bb = 16;
static constexpr int Ss = 2048;
static constexpr int Hh = 1024;

// ---------------------------------------------------------------------------
// Scratch planes (device globals: allocation-free rule)
// ---------------------------------------------------------------------------
__device__ __nv_bfloat16 g_Xhi[(long)Bb * Ss * Hh];
__device__ __nv_bfloat16 g_Xlo[(long)Bb * Ss * Hh];
__device__ __nv_bfloat16 g_Whi[3L * Hh * Hh];
__device__ __nv_bfloat16 g_Wlo[3L * Hh * Hh];
__device__ __nv_bfloat16 g_Qhi[(long)Bb * Ss * Hh];
__device__ __nv_bfloat16 g_Qlo[(long)Bb * Ss * Hh];
__device__ __nv_bfloat16 g_Khi[(long)Bb * Ss * Hh];
__device__ __nv_bfloat16 g_Klo[(long)Bb * Ss * Hh];
__device__ __nv_bfloat16 g_Vthi[(long)Bb * Hh * Ss];   // transposed: [b][h][s]
__device__ __nv_bfloat16 g_Vtlo[(long)Bb * Hh * Ss];
__device__ float         g_S  [(long)Bb * Ss * Ss];    // fp32 scores
__device__ __nv_bfloat16 g_Phi[(long)Bb * Ss * Ss];    // probs hi/lo
__device__ __nv_bfloat16 g_Plo[(long)Bb * Ss * Ss];

// ---------------------------------------------------------------------------
// Helpers
// ---------------------------------------------------------------------------
__device__ __forceinline__ uint32_t smem_u32(const void* p) {
    uint32_t a;
    asm("{ .reg .u64 t; cvta.to.shared.u64 t, %1; cvt.u32.u64 %0, t; }" : "=r"(a) : "l"(p));
    return a;
}

#define CP_ASYNC16(dst, src) \
    asm volatile("cp.async.cg.shared.global [%0], [%1], 16;" \
        :: "r"(dst), "l"(__cvta_generic_to_global(src)) : "memory")
#define CP_COMMIT asm volatile("cp.async.commit_group;" ::: "memory")
#define CP_WAIT(N) asm volatile("cp.async.wait_group %0;" :: "n"(N) : "memory")

__device__ __forceinline__ void ldsm4(uint32_t addr, uint32_t* r) {
    asm volatile("ldmatrix.sync.aligned.m8n8.x4.shared.b16 {%0,%1,%2,%3}, [%4];"
        : "=r"(r[0]), "=r"(r[1]), "=r"(r[2]), "=r"(r[3]) : "r"(addr));
}

__device__ __forceinline__ void mma16816(float* c, const uint32_t* a,
                                         uint32_t b0, uint32_t b1) {
    asm volatile(
        "mma.sync.aligned.m16n8k16.row.col.f32.bf16.bf16.f32 "
        "{%0,%1,%2,%3},{%4,%5,%6,%7},{%8,%9},{%0,%1,%2,%3};"
        : "+f"(c[0]), "+f"(c[1]), "+f"(c[2]), "+f"(c[3])
        : "r"(a[0]), "r"(a[1]), "r"(a[2]), "r"(a[3]), "r"(b0), "r"(b1));
}

__device__ __forceinline__ void bsplit(float x, __nv_bfloat16& h, __nv_bfloat16& l) {
    h = __float2bfloat16_rn(x);
    l = __float2bfloat16_rn(x - __bfloat162float(h));
}
__device__ __forceinline__ uint32_t pack2(__nv_bfloat16 a, __nv_bfloat16 b) {
    __nv_bfloat162 t(a, b);
    return *(uint32_t*)&t;
}

// ---------------------------------------------------------------------------
// Convert: fp32 -> bf16 hi/lo planes
// ---------------------------------------------------------------------------
__global__ __launch_bounds__(256)
void convert_split(const float* __restrict__ in,
                   __nv_bfloat16* __restrict__ hi,
                   __nv_bfloat16* __restrict__ lo) {
    const long i = ((long)blockIdx.x * 256 + threadIdx.x) * 4;
    float4 v = *(const float4*)(in + i);
    __nv_bfloat16 h0, h1, h2, h3, l0, l1, l2, l3;
    bsplit(v.x, h0, l0); bsplit(v.y, h1, l1);
    bsplit(v.z, h2, l2); bsplit(v.w, h3, l3);
    *(uint2*)(hi + i) = make_uint2(pack2(h0, h1), pack2(h2, h3));
    *(uint2*)(lo + i) = make_uint2(pack2(l0, l1), pack2(l2, l3));
}

// ---------------------------------------------------------------------------
// Unified bf16x3 mma.sync GEMM: block 128x128, K-chunk 32, 3-stage cp.async.
// MODE 0: sel 0/1: Q/K = X@W^T + b -> hi/lo planes; sel 2: V (transposed store)
// MODE 1: g_S[b] = mask-fill((Q K^T)/32)  fp32
// MODE 2: out[b] = qmask * (P @ Vt^T)
// ---------------------------------------------------------------------------
static constexpr int PITCH = 80;                 // bytes/row (32 bf16 + pad)
static constexpr int PLANE = 128 * PITCH;        // 10240
static constexpr int STAGE = 4 * PLANE;          // Ahi Alo Bhi Blo = 40960
static constexpr int NSTG  = 3;
static constexpr int SMEM_BYTES = NSTG * STAGE;  // 122880

template<int MODE>
__global__ __launch_bounds__(256, 1)
void mma_gemm(const float* __restrict__ bias, const int* __restrict__ mask,
              float* __restrict__ out, int sel) {
    extern __shared__ char smem[];
    const uint32_t sbase = smem_u32(smem);
    const int tid = threadIdx.x, lane = tid & 31, wid = tid >> 5;
    const int wm = wid & 1, wn = wid >> 1;         // 2 x 4 warps
    const long m0 = (long)blockIdx.x * 128;
    const long n0 = (long)blockIdx.y * 128;
    const int  b  = blockIdx.z;

    const __nv_bfloat16 *Ahi, *Alo, *Bhi, *Blo;
    long ldA, ldB;
    constexpr int NC = (MODE == 2) ? 64 : 32;
    if (MODE == 0) {
        Ahi = g_Xhi; Alo = g_Xlo;
        Bhi = g_Whi + (long)sel * Hh * Hh; Blo = g_Wlo + (long)sel * Hh * Hh;
        ldA = Hh; ldB = Hh;
    } else if (MODE == 1) {
        Ahi = g_Qhi + (long)b * Ss * Hh; Alo = g_Qlo + (long)b * Ss * Hh;
        Bhi = g_Khi + (long)b * Ss * Hh; Blo = g_Klo + (long)b * Ss * Hh;
        ldA = Hh; ldB = Hh;
    } else {
        Ahi = g_Phi + (long)b * Ss * Ss; Alo = g_Plo + (long)b * Ss * Ss;
        Bhi = g_Vthi + (long)b * Hh * Ss; Blo = g_Vtlo + (long)b * Hh * Ss;
        ldA = Ss; ldB = Ss;
    }

    float acc[4][4][4] = {};

    auto issue = [&](int chunk) {
        const uint32_t st = sbase + (chunk % NSTG) * STAGE;
        const long k0 = (long)chunk * 32;
        #pragma unroll
        for (int i = 0; i < 8; ++i) {
            const int plane = i >> 1;                 // uniform per i
            const int q = ((i & 1) << 8) + tid;       // 0..511 within plane
            const int r = q >> 2, c4 = q & 3;
            const uint32_t dst = st + plane * PLANE + r * PITCH + c4 * 16;
            const __nv_bfloat16* src =
                (plane == 0) ? Ahi + (m0 + r) * ldA + k0 + c4 * 8 :
                (plane == 1) ? Alo + (m0 + r) * ldA + k0 + c4 * 8 :
                (plane == 2) ? Bhi + (n0 + r) * ldB + k0 + c4 * 8 :
                               Blo + (n0 + r) * ldB + k0 + c4 * 8;
            CP_ASYNC16(dst, src);
        }
    };

    issue(0); CP_COMMIT;
    issue(1); CP_COMMIT;

    for (int c = 0; c < NC; ++c) {
        if (c + 2 < NC) issue(c + 2);
        CP_COMMIT;
        CP_WAIT(2);
        __syncthreads();

        const uint32_t st = sbase + (c % NSTG) * STAGE;
        const int lr = lane & 15, lc = lane >> 4;
        #pragma unroll
        for (int ks = 0; ks < 2; ++ks) {
            uint32_t ah[4][4], al[4][4], bh[2][4], bl[2][4];
            #pragma unroll
            for (int mt = 0; mt < 4; ++mt) {
                const uint32_t off = (uint32_t)(wm * 64 + mt * 16 + lr) * PITCH + lc * 16 + ks * 32;
                ldsm4(st + off, ah[mt]);
                ldsm4(st + PLANE + off, al[mt]);
            }
            #pragma unroll
            for (int pr = 0; pr < 2; ++pr) {
                const uint32_t off = (uint32_t)(wn * 32 + pr * 16 + lr) * PITCH + lc * 16 + ks * 32;
                ldsm4(st + 2 * PLANE + off, bh[pr]);
                ldsm4(st + 3 * PLANE + off, bl[pr]);
            }
            #pragma unroll
            for (int mt = 0; mt < 4; ++mt)
                #pragma unroll
                for (int nt = 0; nt < 4; ++nt) {
                    const int pr = nt >> 1, sl = nt & 1;
                    mma16816(acc[mt][nt], ah[mt], bh[pr][sl], bh[pr][sl + 2]);
                    mma16816(acc[mt][nt], ah[mt], bl[pr][sl], bl[pr][sl + 2]);
                    mma16816(acc[mt][nt], al[mt], bh[pr][sl], bh[pr][sl + 2]);
                }
        }
        __syncthreads();
    }
    CP_WAIT(0);

    // ------------------------------ epilogues ------------------------------
    const int g = lane >> 2, tq = lane & 3;

    if (MODE == 0 && sel < 2) {
        __nv_bfloat16* Chi = (sel == 0) ? g_Qhi : g_Khi;
        __nv_bfloat16* Clo = (sel == 0) ? g_Qlo : g_Klo;
        #pragma unroll
        for (int mt = 0; mt < 4; ++mt)
            #pragma unroll
            for (int nt = 0; nt < 4; ++nt) {
                const int cc = wn * 32 + nt * 8 + tq * 2;
                const float b0 = bias[n0 + cc], b1 = bias[n0 + cc + 1];
                #pragma unroll
                for (int h = 0; h < 2; ++h) {
                    const long row = m0 + wm * 64 + mt * 16 + g + h * 8;
                    __nv_bfloat16 h0, l0, h1, l1;
                    bsplit(acc[mt][nt][h * 2 + 0] + b0, h0, l0);
                    bsplit(acc[mt][nt][h * 2 + 1] + b1, h1, l1);
                    *(uint32_t*)(Chi + row * Hh + n0 + cc) = pack2(h0, h1);
                    *(uint32_t*)(Clo + row * Hh + n0 + cc) = pack2(l0, l1);
                }
            }
    } else if (MODE == 0) {
        // V: fp32 smem transpose, then coalesced [b][h][s] hi/lo store
        float* stf = (float*)smem;
        #pragma unroll
        for (int mt = 0; mt < 4; ++mt)
            #pragma unroll
            for (int nt = 0; nt < 4; ++nt) {
                const int cc = wn * 32 + nt * 8 + tq * 2;
                const float b0 = bias[n0 + cc], b1 = bias[n0 + cc + 1];
                #pragma unroll
                for (int h = 0; h < 2; ++h) {
                    const int rr = wm * 64 + mt * 16 + g + h * 8;
                    stf[rr * 129 + cc]     = acc[mt][nt][h * 2 + 0] + b0;
                    stf[rr * 129 + cc + 1] = acc[mt][nt][h * 2 + 1] + b1;
                }
            }
        __syncthreads();
        const int m = tid & 127, nb = tid >> 7;
        const long bq = m0 >> 11, s0 = m0 & 2047;
        for (int n2 = 0; n2 < 64; ++n2) {
            const int n = n2 * 2 + nb;
            const float v = stf[m * 129 + n];
            __nv_bfloat16 h, l;
            bsplit(v, h, l);
            const long off = bq * ((long)Hh * Ss) + (n0 + n) * (long)Ss + s0 + m;
            g_Vthi[off] = h;
            g_Vtlo[off] = l;
        }
    } else if (MODE == 1) {
        float* Sp = g_S + (long)b * Ss * Ss;
        #pragma unroll
        for (int mt = 0; mt < 4; ++mt)
            #pragma unroll
            for (int nt = 0; nt < 4; ++nt) {
                const int cc = wn * 32 + nt * 8 + tq * 2;
                const int mk0 = mask[(long)b * Ss + n0 + cc];
                const int mk1 = mask[(long)b * Ss + n0 + cc + 1];
                #pragma unroll
                for (int h = 0; h < 2; ++h) {
                    const long row = m0 + wm * 64 + mt * 16 + g + h * 8;
                    float2 o;
                    o.x = mk0 ? acc[mt][nt][h * 2 + 0] * 0.03125f : -1e9f;
                    o.y = mk1 ? acc[mt][nt][h * 2 + 1] * 0.03125f : -1e9f;
                    *(float2*)(Sp + row * Ss + n0 + cc) = o;
                }
            }
    } else {
        #pragma unroll
        for (int mt = 0; mt < 4; ++mt)
            #pragma unroll
            for (int h = 0; h < 2; ++h) {
                const long row = m0 + wm * 64 + mt * 16 + g + h * 8;
                const int qm = mask[(long)b * Ss + row];
                #pragma unroll
                for (int nt = 0; nt < 4; ++nt) {
                    const int cc = wn * 32 + nt * 8 + tq * 2;
                    float2 o;
                    o.x = qm ? acc[mt][nt][h * 2 + 0] : 0.0f;
                    o.y = qm ? acc[mt][nt][h * 2 + 1] : 0.0f;
                    *(float2*)(out + ((long)b * Ss + row) * Hh + n0 + cc) = o;
                }
            }
    }
}

// ---------------------------------------------------------------------------
// Row softmax (S=2048) reading fp32 g_S, writing bf16 hi/lo prob planes.
// ---------------------------------------------------------------------------
__device__ __forceinline__ float warp_max(float v) {
    #pragma unroll
    for (int o = 16; o > 0; o >>= 1) v = fmaxf(v, __shfl_xor_sync(0xffffffffu, v, o));
    return v;
}
__device__ __forceinline__ float warp_sum(float v) {
    #pragma unroll
    for (int o = 16; o > 0; o >>= 1) v += __shfl_xor_sync(0xffffffffu, v, o);
    return v;
}

__global__ __launch_bounds__(256)
void softmax_kernel() {
    const long row = blockIdx.x;
    const float* __restrict__ p = g_S + row * (long)Ss;
    const int tid = threadIdx.x, lane = tid & 31, wid = tid >> 5;

    float4 v0 = ((const float4*)p)[tid];
    float4 v1 = ((const float4*)p)[tid + 256];
    float x[8] = {v0.x, v0.y, v0.z, v0.w, v1.x, v1.y, v1.z, v1.w};

    __shared__ float sh[8];

    float mx = x[0];
    #pragma unroll
    for (int i = 1; i < 8; ++i) mx = fmaxf(mx, x[i]);
    mx = warp_max(mx);
    if (lane == 0) sh[wid] = mx;
    __syncthreads();
    if (tid < 32) {
        float t = (lane < 8) ? sh[lane] : -CUDART_INF_F;
        t = warp_max(t);
        if (lane == 0) sh[0] = t;
    }
    __syncthreads();
    const float bmax = sh[0];
    __syncthreads();

    float e[8], s = 0.f;
    #pragma unroll
    for (int i = 0; i < 8; ++i) { e[i] = __expf(x[i] - bmax); s += e[i]; }
    s = warp_sum(s);
    if (lane == 0) sh[wid] = s;
    __syncthreads();
    if (tid < 32) {
        float t = (lane < 8) ? sh[lane] : 0.f;
        t = warp_sum(t);
        if (lane == 0) sh[0] = t;
    }
    __syncthreads();
    const float inv = 1.0f / sh[0];

    __nv_bfloat16 h[8], l[8];
    #pragma unroll
    for (int i = 0; i < 8; ++i) bsplit(e[i] * inv, h[i], l[i]);

    __nv_bfloat16* Phi = g_Phi + row * (long)Ss;
    __nv_bfloat16* Plo = g_Plo + row * (long)Ss;
    *(uint2*)(Phi + 4 * tid)        = make_uint2(pack2(h[0], h[1]), pack2(h[2], h[3]));
    *(uint2*)(Phi + 1024 + 4 * tid) = make_uint2(pack2(h[4], h[5]), pack2(h[6], h[7]));
    *(uint2*)(Plo + 4 * tid)        = make_uint2(pack2(l[0], l[1]), pack2(l[2], l[3]));
    *(uint2*)(Plo + 1024 + 4 * tid) = make_uint2(pack2(l[4], l[5]), pack2(l[6], l[7]));
}

// ---------------------------------------------------------------------------
extern "C" void kernel_launch(void* const* d_in, const int* in_sizes, int n_in,
                              void* d_out, int out_size) {
    const float* X    = (const float*)d_in[0];
    const int*   mask = (const int*)  d_in[1];
    const float* Wq   = (const float*)d_in[2];
    const float* bq   = (const float*)d_in[3];
    const float* Wk   = (const float*)d_in[4];
    const float* bk   = (const float*)d_in[5];
    const float* Wv   = (const float*)d_in[6];
    const float* bv   = (const float*)d_in[7];
    float* out = (float*)d_out;

    static bool attr_done = false;
    if (!attr_done) {
        cudaFuncSetAttribute(mma_gemm<0>, cudaFuncAttributeMaxDynamicSharedMemorySize, SMEM_BYTES);
        cudaFuncSetAttribute(mma_gemm<1>, cudaFuncAttributeMaxDynamicSharedMemorySize, SMEM_BYTES);
        cudaFuncSetAttribute(mma_gemm<2>, cudaFuncAttributeMaxDynamicSharedMemorySize, SMEM_BYTES);
        attr_done = true;
    }

    void *pXhi, *pXlo, *pWhi, *pWlo;
    cudaGetSymbolAddress(&pXhi, g_Xhi);
    cudaGetSymbolAddress(&pXlo, g_Xlo);
    cudaGetSymbolAddress(&pWhi, g_Whi);
    cudaGetSymbolAddress(&pWlo, g_Wlo);

    dim3 blk(256);

    // Split X and the three weight matrices into bf16 hi/lo planes
    convert_split<<<(long)Bb * Ss * Hh / 1024, blk>>>(X, (__nv_bfloat16*)pXhi, (__nv_bfloat16*)pXlo);
    convert_split<<<(long)Hh * Hh / 1024, blk>>>(Wq, (__nv_bfloat16*)pWhi, (__nv_bfloat16*)pWlo);
    convert_split<<<(long)Hh * Hh / 1024, blk>>>(Wk, (__nv_bfloat16*)pWhi + (long)Hh * Hh,
                                                     (__nv_bfloat16*)pWlo + (long)Hh * Hh);
    convert_split<<<(long)Hh * Hh / 1024, blk>>>(Wv, (__nv_bfloat16*)pWhi + 2L * Hh * Hh,
                                                     (__nv_bfloat16*)pWlo + 2L * Hh * Hh);

    // QKV projections (V stored transposed)
    dim3 grid_qkv((Bb * Ss) / 128, Hh / 128, 1);
    mma_gemm<0><<<grid_qkv, blk, SMEM_BYTES>>>(bq, nullptr, nullptr, 0);
    mma_gemm<0><<<grid_qkv, blk, SMEM_BYTES>>>(bk, nullptr, nullptr, 1);
    mma_gemm<0><<<grid_qkv, blk, SMEM_BYTES>>>(bv, nullptr, nullptr, 2);

    // Scores
    dim3 grid_sc(Ss / 128, Ss / 128, Bb);
    mma_gemm<1><<<grid_sc, blk, SMEM_BYTES>>>(nullptr, mask, nullptr, 0);

    // Softmax -> prob hi/lo planes
    softmax_kernel<<<Bb * Ss, blk>>>();

    // P @ V^T with query-mask epilogue
    dim3 grid_pv(Ss / 128, Hh / 128, Bb);
    mma_gemm<2><<<grid_pv, blk, SMEM_BYTES>>>(nullptr, mask, out, 0);
}

// round 5
// speedup vs baseline: 1.0010x; 1.0010x over previous
#include <cuda_runtime.h>
#include <cuda_bf16.h>
#include <cstdint>
#include <math_constants.h>

static constexpr int Bb = 16;
static constexpr int Ss = 2048;
static constexpr int Hh = 1024;

// ---------------------------------------------------------------------------
// Scratch planes (device globals: allocation-free rule)
// ---------------------------------------------------------------------------
__device__ __nv_bfloat16 g_Xhi[(long)Bb * Ss * Hh];
__device__ __nv_bfloat16 g_Xlo[(long)Bb * Ss * Hh];
__device__ __nv_bfloat16 g_Whi[3L * Hh * Hh];
__device__ __nv_bfloat16 g_Wlo[3L * Hh * Hh];
__device__ __nv_bfloat16 g_Qhi[(long)Bb * Ss * Hh];
__device__ __nv_bfloat16 g_Qlo[(long)Bb * Ss * Hh];
__device__ __nv_bfloat16 g_Khi[(long)Bb * Ss * Hh];
__device__ __nv_bfloat16 g_Klo[(long)Bb * Ss * Hh];
__device__ __nv_bfloat16 g_Vthi[(long)Bb * Hh * Ss];   // transposed: [b][h][s]
__device__ __nv_bfloat16 g_Vtlo[(long)Bb * Hh * Ss];
__device__ float         g_S  [(long)Bb * Ss * Ss];    // fp32 scores
__device__ __nv_bfloat16 g_Phi[(long)Bb * Ss * Ss];    // probs hi/lo
__device__ __nv_bfloat16 g_Plo[(long)Bb * Ss * Ss];

// ---------------------------------------------------------------------------
// Helpers
// ---------------------------------------------------------------------------
__device__ __forceinline__ uint32_t smem_u32(const void* p) {
    uint32_t a;
    asm("{ .reg .u64 t; cvta.to.shared.u64 t, %1; cvt.u32.u64 %0, t; }" : "=r"(a) : "l"(p));
    return a;
}

#define CP_ASYNC16(dst, src) \
    asm volatile("cp.async.cg.shared.global [%0], [%1], 16;" \
        :: "r"(dst), "l"(__cvta_generic_to_global(src)) : "memory")
#define CP_COMMIT asm volatile("cp.async.commit_group;" ::: "memory")
#define CP_WAIT(N) asm volatile("cp.async.wait_group %0;" :: "n"(N) : "memory")

__device__ __forceinline__ void ldsm4(uint32_t addr, uint32_t* r) {
    asm volatile("ldmatrix.sync.aligned.m8n8.x4.shared.b16 {%0,%1,%2,%3}, [%4];"
        : "=r"(r[0]), "=r"(r[1]), "=r"(r[2]), "=r"(r[3]) : "r"(addr));
}

__device__ __forceinline__ void mma16816(float* c, const uint32_t* a,
                                         uint32_t b0, uint32_t b1) {
    asm volatile(
        "mma.sync.aligned.m16n8k16.row.col.f32.bf16.bf16.f32 "
        "{%0,%1,%2,%3},{%4,%5,%6,%7},{%8,%9},{%0,%1,%2,%3};"
        : "+f"(c[0]), "+f"(c[1]), "+f"(c[2]), "+f"(c[3])
        : "r"(a[0]), "r"(a[1]), "r"(a[2]), "r"(a[3]), "r"(b0), "r"(b1));
}

__device__ __forceinline__ void bsplit(float x, __nv_bfloat16& h, __nv_bfloat16& l) {
    h = __float2bfloat16_rn(x);
    l = __float2bfloat16_rn(x - __bfloat162float(h));
}
__device__ __forceinline__ uint32_t pack2(__nv_bfloat16 a, __nv_bfloat16 b) {
    __nv_bfloat162 t(a, b);
    return *(uint32_t*)&t;
}

// ---------------------------------------------------------------------------
// Convert: fp32 -> bf16 hi/lo planes
// ---------------------------------------------------------------------------
__global__ __launch_bounds__(256)
void convert_split(const float* __restrict__ in,
                   __nv_bfloat16* __restrict__ hi,
                   __nv_bfloat16* __restrict__ lo) {
    const long i = ((long)blockIdx.x * 256 + threadIdx.x) * 4;
    float4 v = *(const float4*)(in + i);
    __nv_bfloat16 h0, h1, h2, h3, l0, l1, l2, l3;
    bsplit(v.x, h0, l0); bsplit(v.y, h1, l1);
    bsplit(v.z, h2, l2); bsplit(v.w, h3, l3);
    *(uint2*)(hi + i) = make_uint2(pack2(h0, h1), pack2(h2, h3));
    *(uint2*)(lo + i) = make_uint2(pack2(l0, l1), pack2(l2, l3));
}

// ---------------------------------------------------------------------------
// Unified bf16x3 mma.sync GEMM: block 128x128, K-chunk 32, 3-stage cp.async.
// MODE 0: sel 0/1: Q/K = X@W^T + b -> hi/lo planes; sel 2: V (transposed store)
// MODE 1: g_S[b] = mask-fill((Q K^T)/32)  fp32
// MODE 2: out[b] = qmask * (P @ Vt^T)
// ---------------------------------------------------------------------------
static constexpr int PITCH = 80;                 // bytes/row (32 bf16 + pad)
static constexpr int PLANE = 128 * PITCH;        // 10240
static constexpr int STAGE = 4 * PLANE;          // Ahi Alo Bhi Blo = 40960
static constexpr int NSTG  = 3;
static constexpr int SMEM_BYTES = NSTG * STAGE;  // 122880

template<int MODE>
__global__ __launch_bounds__(256, 1)
void mma_gemm(const float* __restrict__ bias, const int* __restrict__ mask,
              float* __restrict__ out, int sel) {
    extern __shared__ char smem[];
    const uint32_t sbase = smem_u32(smem);
    const int tid = threadIdx.x, lane = tid & 31, wid = tid >> 5;
    const int wm = wid & 1, wn = wid >> 1;         // 2 x 4 warps
    const long m0 = (long)blockIdx.x * 128;
    const long n0 = (long)blockIdx.y * 128;
    const int  b  = blockIdx.z;

    const __nv_bfloat16 *Ahi, *Alo, *Bhi, *Blo;
    long ldA, ldB;
    constexpr int NC = (MODE == 2) ? 64 : 32;
    if (MODE == 0) {
        Ahi = g_Xhi; Alo = g_Xlo;
        Bhi = g_Whi + (long)sel * Hh * Hh; Blo = g_Wlo + (long)sel * Hh * Hh;
        ldA = Hh; ldB = Hh;
    } else if (MODE == 1) {
        Ahi = g_Qhi + (long)b * Ss * Hh; Alo = g_Qlo + (long)b * Ss * Hh;
        Bhi = g_Khi + (long)b * Ss * Hh; Blo = g_Klo + (long)b * Ss * Hh;
        ldA = Hh; ldB = Hh;
    } else {
        Ahi = g_Phi + (long)b * Ss * Ss; Alo = g_Plo + (long)b * Ss * Ss;
        Bhi = g_Vthi + (long)b * Hh * Ss; Blo = g_Vtlo + (long)b * Hh * Ss;
        ldA = Ss; ldB = Ss;
    }

    float acc[4][4][4] = {};

    auto issue = [&](int chunk) {
        const uint32_t st = sbase + (chunk % NSTG) * STAGE;
        const long k0 = (long)chunk * 32;
        #pragma unroll
        for (int i = 0; i < 8; ++i) {
            const int plane = i >> 1;                 // uniform per i
            const int q = ((i & 1) << 8) + tid;       // 0..511 within plane
            const int r = q >> 2, c4 = q & 3;
            const uint32_t dst = st + plane * PLANE + r * PITCH + c4 * 16;
            const __nv_bfloat16* src =
                (plane == 0) ? Ahi + (m0 + r) * ldA + k0 + c4 * 8 :
                (plane == 1) ? Alo + (m0 + r) * ldA + k0 + c4 * 8 :
                (plane == 2) ? Bhi + (n0 + r) * ldB + k0 + c4 * 8 :
                               Blo + (n0 + r) * ldB + k0 + c4 * 8;
            CP_ASYNC16(dst, src);
        }
    };

    issue(0); CP_COMMIT;
    issue(1); CP_COMMIT;

    for (int c = 0; c < NC; ++c) {
        if (c + 2 < NC) issue(c + 2);
        CP_COMMIT;
        CP_WAIT(2);
        __syncthreads();

        const uint32_t st = sbase + (c % NSTG) * STAGE;
        const int lr = lane & 15, lc = lane >> 4;
        #pragma unroll
        for (int ks = 0; ks < 2; ++ks) {
            uint32_t ah[4][4], al[4][4], bh[2][4], bl[2][4];
            #pragma unroll
            for (int mt = 0; mt < 4; ++mt) {
                const uint32_t off = (uint32_t)(wm * 64 + mt * 16 + lr) * PITCH + lc * 16 + ks * 32;
                ldsm4(st + off, ah[mt]);
                ldsm4(st + PLANE + off, al[mt]);
            }
            #pragma unroll
            for (int pr = 0; pr < 2; ++pr) {
                const uint32_t off = (uint32_t)(wn * 32 + pr * 16 + lr) * PITCH + lc * 16 + ks * 32;
                ldsm4(st + 2 * PLANE + off, bh[pr]);
                ldsm4(st + 3 * PLANE + off, bl[pr]);
            }
            #pragma unroll
            for (int mt = 0; mt < 4; ++mt)
                #pragma unroll
                for (int nt = 0; nt < 4; ++nt) {
                    const int pr = nt >> 1, sl = nt & 1;
                    mma16816(acc[mt][nt], ah[mt], bh[pr][sl], bh[pr][sl + 2]);
                    mma16816(acc[mt][nt], ah[mt], bl[pr][sl], bl[pr][sl + 2]);
                    mma16816(acc[mt][nt], al[mt], bh[pr][sl], bh[pr][sl + 2]);
                }
        }
        __syncthreads();
    }
    CP_WAIT(0);

    // ------------------------------ epilogues ------------------------------
    const int g = lane >> 2, tq = lane & 3;

    if (MODE == 0 && sel < 2) {
        __nv_bfloat16* Chi = (sel == 0) ? g_Qhi : g_Khi;
        __nv_bfloat16* Clo = (sel == 0) ? g_Qlo : g_Klo;
        #pragma unroll
        for (int mt = 0; mt < 4; ++mt)
            #pragma unroll
            for (int nt = 0; nt < 4; ++nt) {
                const int cc = wn * 32 + nt * 8 + tq * 2;
                const float b0 = bias[n0 + cc], b1 = bias[n0 + cc + 1];
                #pragma unroll
                for (int h = 0; h < 2; ++h) {
                    const long row = m0 + wm * 64 + mt * 16 + g + h * 8;
                    __nv_bfloat16 h0, l0, h1, l1;
                    bsplit(acc[mt][nt][h * 2 + 0] + b0, h0, l0);
                    bsplit(acc[mt][nt][h * 2 + 1] + b1, h1, l1);
                    *(uint32_t*)(Chi + row * Hh + n0 + cc) = pack2(h0, h1);
                    *(uint32_t*)(Clo + row * Hh + n0 + cc) = pack2(l0, l1);
                }
            }
    } else if (MODE == 0) {
        // V: fp32 smem transpose, then coalesced [b][h][s] hi/lo store
        float* stf = (float*)smem;
        #pragma unroll
        for (int mt = 0; mt < 4; ++mt)
            #pragma unroll
            for (int nt = 0; nt < 4; ++nt) {
                const int cc = wn * 32 + nt * 8 + tq * 2;
                const float b0 = bias[n0 + cc], b1 = bias[n0 + cc + 1];
                #pragma unroll
                for (int h = 0; h < 2; ++h) {
                    const int rr = wm * 64 + mt * 16 + g + h * 8;
                    stf[rr * 129 + cc]     = acc[mt][nt][h * 2 + 0] + b0;
                    stf[rr * 129 + cc + 1] = acc[mt][nt][h * 2 + 1] + b1;
                }
            }
        __syncthreads();
        const int m = tid & 127, nb = tid >> 7;
        const long bq = m0 >> 11, s0 = m0 & 2047;
        for (int n2 = 0; n2 < 64; ++n2) {
            const int n = n2 * 2 + nb;
            const float v = stf[m * 129 + n];
            __nv_bfloat16 h, l;
            bsplit(v, h, l);
            const long off = bq * ((long)Hh * Ss) + (n0 + n) * (long)Ss + s0 + m;
            g_Vthi[off] = h;
            g_Vtlo[off] = l;
        }
    } else if (MODE == 1) {
        float* Sp = g_S + (long)b * Ss * Ss;
        #pragma unroll
        for (int mt = 0; mt < 4; ++mt)
            #pragma unroll
            for (int nt = 0; nt < 4; ++nt) {
                const int cc = wn * 32 + nt * 8 + tq * 2;
                const int mk0 = mask[(long)b * Ss + n0 + cc];
                const int mk1 = mask[(long)b * Ss + n0 + cc + 1];
                #pragma unroll
                for (int h = 0; h < 2; ++h) {
                    const long row = m0 + wm * 64 + mt * 16 + g + h * 8;
                    float2 o;
                    o.x = mk0 ? acc[mt][nt][h * 2 + 0] * 0.03125f : -1e9f;
                    o.y = mk1 ? acc[mt][nt][h * 2 + 1] * 0.03125f : -1e9f;
                    *(float2*)(Sp + row * Ss + n0 + cc) = o;
                }
            }
    } else {
        #pragma unroll
        for (int mt = 0; mt < 4; ++mt)
            #pragma unroll
            for (int h = 0; h < 2; ++h) {
                const long row = m0 + wm * 64 + mt * 16 + g + h * 8;
                const int qm = mask[(long)b * Ss + row];
                #pragma unroll
                for (int nt = 0; nt < 4; ++nt) {
                    const int cc = wn * 32 + nt * 8 + tq * 2;
                    float2 o;
                    o.x = qm ? acc[mt][nt][h * 2 + 0] : 0.0f;
                    o.y = qm ? acc[mt][nt][h * 2 + 1] : 0.0f;
                    *(float2*)(out + ((long)b * Ss + row) * Hh + n0 + cc) = o;
                }
            }
    }
}

// ---------------------------------------------------------------------------
// Row softmax (S=2048) reading fp32 g_S, writing bf16 hi/lo prob planes.
// ---------------------------------------------------------------------------
__device__ __forceinline__ float warp_max(float v) {
    #pragma unroll
    for (int o = 16; o > 0; o >>= 1) v = fmaxf(v, __shfl_xor_sync(0xffffffffu, v, o));
    return v;
}
__device__ __forceinline__ float warp_sum(float v) {
    #pragma unroll
    for (int o = 16; o > 0; o >>= 1) v += __shfl_xor_sync(0xffffffffu, v, o);
    return v;
}

__global__ __launch_bounds__(256)
void softmax_kernel() {
    const long row = blockIdx.x;
    const float* __restrict__ p = g_S + row * (long)Ss;
    const int tid = threadIdx.x, lane = tid & 31, wid = tid >> 5;

    float4 v0 = ((const float4*)p)[tid];
    float4 v1 = ((const float4*)p)[tid + 256];
    float x[8] = {v0.x, v0.y, v0.z, v0.w, v1.x, v1.y, v1.z, v1.w};

    __shared__ float sh[8];

    float mx = x[0];
    #pragma unroll
    for (int i = 1; i < 8; ++i) mx = fmaxf(mx, x[i]);
    mx = warp_max(mx);
    if (lane == 0) sh[wid] = mx;
    __syncthreads();
    if (tid < 32) {
        float t = (lane < 8) ? sh[lane] : -CUDART_INF_F;
        t = warp_max(t);
        if (lane == 0) sh[0] = t;
    }
    __syncthreads();
    const float bmax = sh[0];
    __syncthreads();

    float e[8], s = 0.f;
    #pragma unroll
    for (int i = 0; i < 8; ++i) { e[i] = __expf(x[i] - bmax); s += e[i]; }
    s = warp_sum(s);
    if (lane == 0) sh[wid] = s;
    __syncthreads();
    if (tid < 32) {
        float t = (lane < 8) ? sh[lane] : 0.f;
        t = warp_sum(t);
        if (lane == 0) sh[0] = t;
    }
    __syncthreads();
    const float inv = 1.0f / sh[0];

    __nv_bfloat16 h[8], l[8];
    #pragma unroll
    for (int i = 0; i < 8; ++i) bsplit(e[i] * inv, h[i], l[i]);

    __nv_bfloat16* Phi = g_Phi + row * (long)Ss;
    __nv_bfloat16* Plo = g_Plo + row * (long)Ss;
    *(uint2*)(Phi + 4 * tid)        = make_uint2(pack2(h[0], h[1]), pack2(h[2], h[3]));
    *(uint2*)(Phi + 1024 + 4 * tid) = make_uint2(pack2(h[4], h[5]), pack2(h[6], h[7]));
    *(uint2*)(Plo + 4 * tid)        = make_uint2(pack2(l[0], l[1]), pack2(l[2], l[3]));
    *(uint2*)(Plo + 1024 + 4 * tid) = make_uint2(pack2(l[4], l[5]), pack2(l[6], l[7]));
}

// ---------------------------------------------------------------------------
extern "C" void kernel_launch(void* const* d_in, const int* in_sizes, int n_in,
                              void* d_out, int out_size) {
    const float* X    = (const float*)d_in[0];
    const int*   mask = (const int*)  d_in[1];
    const float* Wq   = (const float*)d_in[2];
    const float* bq   = (const float*)d_in[3];
    const float* Wk   = (const float*)d_in[4];
    const float* bk   = (const float*)d_in[5];
    const float* Wv   = (const float*)d_in[6];
    const float* bv   = (const float*)d_in[7];
    float* out = (float*)d_out;

    static bool attr_done = false;
    if (!attr_done) {
        cudaFuncSetAttribute(mma_gemm<0>, cudaFuncAttributeMaxDynamicSharedMemorySize, SMEM_BYTES);
        cudaFuncSetAttribute(mma_gemm<1>, cudaFuncAttributeMaxDynamicSharedMemorySize, SMEM_BYTES);
        cudaFuncSetAttribute(mma_gemm<2>, cudaFuncAttributeMaxDynamicSharedMemorySize, SMEM_BYTES);
        attr_done = true;
    }

    void *pXhi, *pXlo, *pWhi, *pWlo;
    cudaGetSymbolAddress(&pXhi, g_Xhi);
    cudaGetSymbolAddress(&pXlo, g_Xlo);
    cudaGetSymbolAddress(&pWhi, g_Whi);
    cudaGetSymbolAddress(&pWlo, g_Wlo);

    dim3 blk(256);

    // Split X and the three weight matrices into bf16 hi/lo planes
    convert_split<<<(long)Bb * Ss * Hh / 1024, blk>>>(X, (__nv_bfloat16*)pXhi, (__nv_bfloat16*)pXlo);
    convert_split<<<(long)Hh * Hh / 1024, blk>>>(Wq, (__nv_bfloat16*)pWhi, (__nv_bfloat16*)pWlo);
    convert_split<<<(long)Hh * Hh / 1024, blk>>>(Wk, (__nv_bfloat16*)pWhi + (long)Hh * Hh,
                                                     (__nv_bfloat16*)pWlo + (long)Hh * Hh);
    convert_split<<<(long)Hh * Hh / 1024, blk>>>(Wv, (__nv_bfloat16*)pWhi + 2L * Hh * Hh,
                                                     (__nv_bfloat16*)pWlo + 2L * Hh * Hh);

    // QKV projections (V stored transposed)
    dim3 grid_qkv((Bb * Ss) / 128, Hh / 128, 1);
    mma_gemm<0><<<grid_qkv, blk, SMEM_BYTES>>>(bq, nullptr, nullptr, 0);
    mma_gemm<0><<<grid_qkv, blk, SMEM_BYTES>>>(bk, nullptr, nullptr, 1);
    mma_gemm<0><<<grid_qkv, blk, SMEM_BYTES>>>(bv, nullptr, nullptr, 2);

    // Scores
    dim3 grid_sc(Ss / 128, Ss / 128, Bb);
    mma_gemm<1><<<grid_sc, blk, SMEM_BYTES>>>(nullptr, mask, nullptr, 0);

    // Softmax -> prob hi/lo planes
    softmax_kernel<<<Bb * Ss, blk>>>();

    // P @ V^T with query-mask epilogue
    dim3 grid_pv(Ss / 128, Hh / 128, Bb);
    mma_gemm<2><<<grid_pv, blk, SMEM_BYTES>>>(nullptr, mask, out, 0);
}

// round 6
// speedup vs baseline: 1.0012x; 1.0002x over previous
#include <cuda_runtime.h>
#include <cuda_bf16.h>
#include <cstdint>
#include <math_constants.h>

static constexpr int Bb = 16;
static constexpr int Ss = 2048;
static constexpr int Hh = 1024;

// ---------------------------------------------------------------------------
// Scratch planes (device globals: allocation-free rule)
// ---------------------------------------------------------------------------
__device__ __nv_bfloat16 g_Xhi[(long)Bb * Ss * Hh];
__device__ __nv_bfloat16 g_Xlo[(long)Bb * Ss * Hh];
__device__ __nv_bfloat16 g_Whi[3L * Hh * Hh];
__device__ __nv_bfloat16 g_Wlo[3L * Hh * Hh];
__device__ __nv_bfloat16 g_Qhi[(long)Bb * Ss * Hh];
__device__ __nv_bfloat16 g_Qlo[(long)Bb * Ss * Hh];
__device__ __nv_bfloat16 g_Khi[(long)Bb * Ss * Hh];
__device__ __nv_bfloat16 g_Klo[(long)Bb * Ss * Hh];
__device__ __nv_bfloat16 g_Vthi[(long)Bb * Hh * Ss];   // transposed: [b][h][s]
__device__ __nv_bfloat16 g_Vtlo[(long)Bb * Hh * Ss];
__device__ float         g_S  [(long)Bb * Ss * Ss];    // fp32 scores
__device__ __nv_bfloat16 g_Phi[(long)Bb * Ss * Ss];    // probs hi/lo
__device__ __nv_bfloat16 g_Plo[(long)Bb * Ss * Ss];

// ---------------------------------------------------------------------------
// Helpers
// ---------------------------------------------------------------------------
__device__ __forceinline__ uint32_t smem_u32(const void* p) {
    uint32_t a;
    asm("{ .reg .u64 t; cvta.to.shared.u64 t, %1; cvt.u32.u64 %0, t; }" : "=r"(a) : "l"(p));
    return a;
}

#define CP_ASYNC16(dst, src) \
    asm volatile("cp.async.cg.shared.global [%0], [%1], 16;" \
        :: "r"(dst), "l"(__cvta_generic_to_global(src)) : "memory")
#define CP_COMMIT asm volatile("cp.async.commit_group;" ::: "memory")
#define CP_WAIT(N) asm volatile("cp.async.wait_group %0;" :: "n"(N) : "memory")

__device__ __forceinline__ void ldsm4(uint32_t addr, uint32_t* r) {
    asm volatile("ldmatrix.sync.aligned.m8n8.x4.shared.b16 {%0,%1,%2,%3}, [%4];"
        : "=r"(r[0]), "=r"(r[1]), "=r"(r[2]), "=r"(r[3]) : "r"(addr));
}

__device__ __forceinline__ void mma16816(float* c, const uint32_t* a,
                                         uint32_t b0, uint32_t b1) {
    asm volatile(
        "mma.sync.aligned.m16n8k16.row.col.f32.bf16.bf16.f32 "
        "{%0,%1,%2,%3},{%4,%5,%6,%7},{%8,%9},{%0,%1,%2,%3};"
        : "+f"(c[0]), "+f"(c[1]), "+f"(c[2]), "+f"(c[3])
        : "r"(a[0]), "r"(a[1]), "r"(a[2]), "r"(a[3]), "r"(b0), "r"(b1));
}

__device__ __forceinline__ void bsplit(float x, __nv_bfloat16& h, __nv_bfloat16& l) {
    h = __float2bfloat16_rn(x);
    l = __float2bfloat16_rn(x - __bfloat162float(h));
}
__device__ __forceinline__ uint32_t pack2(__nv_bfloat16 a, __nv_bfloat16 b) {
    __nv_bfloat162 t(a, b);
    return *(uint32_t*)&t;
}

// ---------------------------------------------------------------------------
// Convert: fp32 -> bf16 hi/lo planes
// ---------------------------------------------------------------------------
__global__ __launch_bounds__(256)
void convert_split(const float* __restrict__ in,
                   __nv_bfloat16* __restrict__ hi,
                   __nv_bfloat16* __restrict__ lo) {
    const long i = ((long)blockIdx.x * 256 + threadIdx.x) * 4;
    float4 v = *(const float4*)(in + i);
    __nv_bfloat16 h0, h1, h2, h3, l0, l1, l2, l3;
    bsplit(v.x, h0, l0); bsplit(v.y, h1, l1);
    bsplit(v.z, h2, l2); bsplit(v.w, h3, l3);
    *(uint2*)(hi + i) = make_uint2(pack2(h0, h1), pack2(h2, h3));
    *(uint2*)(lo + i) = make_uint2(pack2(l0, l1), pack2(l2, l3));
}

// ---------------------------------------------------------------------------
// Unified bf16x3 mma.sync GEMM: block 128x128, K-chunk 32, 3-stage cp.async.
// MODE 0: sel 0/1: Q/K = X@W^T + b -> hi/lo planes; sel 2: V (transposed store)
// MODE 1: g_S[b] = mask-fill((Q K^T)/32)  fp32
// MODE 2: out[b] = qmask * (P @ Vt^T)
// ---------------------------------------------------------------------------
static constexpr int PITCH = 80;                 // bytes/row (32 bf16 + pad)
static constexpr int PLANE = 128 * PITCH;        // 10240
static constexpr int STAGE = 4 * PLANE;          // Ahi Alo Bhi Blo = 40960
static constexpr int NSTG  = 3;
static constexpr int SMEM_BYTES = NSTG * STAGE;  // 122880

template<int MODE>
__global__ __launch_bounds__(256, 1)
void mma_gemm(const float* __restrict__ bias, const int* __restrict__ mask,
              float* __restrict__ out, int sel) {
    extern __shared__ char smem[];
    const uint32_t sbase = smem_u32(smem);
    const int tid = threadIdx.x, lane = tid & 31, wid = tid >> 5;
    const int wm = wid & 1, wn = wid >> 1;         // 2 x 4 warps
    const long m0 = (long)blockIdx.x * 128;
    const long n0 = (long)blockIdx.y * 128;
    const int  b  = blockIdx.z;

    const __nv_bfloat16 *Ahi, *Alo, *Bhi, *Blo;
    long ldA, ldB;
    constexpr int NC = (MODE == 2) ? 64 : 32;
    if (MODE == 0) {
        Ahi = g_Xhi; Alo = g_Xlo;
        Bhi = g_Whi + (long)sel * Hh * Hh; Blo = g_Wlo + (long)sel * Hh * Hh;
        ldA = Hh; ldB = Hh;
    } else if (MODE == 1) {
        Ahi = g_Qhi + (long)b * Ss * Hh; Alo = g_Qlo + (long)b * Ss * Hh;
        Bhi = g_Khi + (long)b * Ss * Hh; Blo = g_Klo + (long)b * Ss * Hh;
        ldA = Hh; ldB = Hh;
    } else {
        Ahi = g_Phi + (long)b * Ss * Ss; Alo = g_Plo + (long)b * Ss * Ss;
        Bhi = g_Vthi + (long)b * Hh * Ss; Blo = g_Vtlo + (long)b * Hh * Ss;
        ldA = Ss; ldB = Ss;
    }

    float acc[4][4][4] = {};

    auto issue = [&](int chunk) {
        const uint32_t st = sbase + (chunk % NSTG) * STAGE;
        const long k0 = (long)chunk * 32;
        #pragma unroll
        for (int i = 0; i < 8; ++i) {
            const int plane = i >> 1;                 // uniform per i
            const int q = ((i & 1) << 8) + tid;       // 0..511 within plane
            const int r = q >> 2, c4 = q & 3;
            const uint32_t dst = st + plane * PLANE + r * PITCH + c4 * 16;
            const __nv_bfloat16* src =
                (plane == 0) ? Ahi + (m0 + r) * ldA + k0 + c4 * 8 :
                (plane == 1) ? Alo + (m0 + r) * ldA + k0 + c4 * 8 :
                (plane == 2) ? Bhi + (n0 + r) * ldB + k0 + c4 * 8 :
                               Blo + (n0 + r) * ldB + k0 + c4 * 8;
            CP_ASYNC16(dst, src);
        }
    };

    issue(0); CP_COMMIT;
    issue(1); CP_COMMIT;

    for (int c = 0; c < NC; ++c) {
        if (c + 2 < NC) issue(c + 2);
        CP_COMMIT;
        CP_WAIT(2);
        __syncthreads();

        const uint32_t st = sbase + (c % NSTG) * STAGE;
        const int lr = lane & 15, lc = lane >> 4;
        #pragma unroll
        for (int ks = 0; ks < 2; ++ks) {
            uint32_t ah[4][4], al[4][4], bh[2][4], bl[2][4];
            #pragma unroll
            for (int mt = 0; mt < 4; ++mt) {
                const uint32_t off = (uint32_t)(wm * 64 + mt * 16 + lr) * PITCH + lc * 16 + ks * 32;
                ldsm4(st + off, ah[mt]);
                ldsm4(st + PLANE + off, al[mt]);
            }
            #pragma unroll
            for (int pr = 0; pr < 2; ++pr) {
                const uint32_t off = (uint32_t)(wn * 32 + pr * 16 + lr) * PITCH + lc * 16 + ks * 32;
                ldsm4(st + 2 * PLANE + off, bh[pr]);
                ldsm4(st + 3 * PLANE + off, bl[pr]);
            }
            #pragma unroll
            for (int mt = 0; mt < 4; ++mt)
                #pragma unroll
                for (int nt = 0; nt < 4; ++nt) {
                    const int pr = nt >> 1, sl = nt & 1;
                    mma16816(acc[mt][nt], ah[mt], bh[pr][sl], bh[pr][sl + 2]);
                    mma16816(acc[mt][nt], ah[mt], bl[pr][sl], bl[pr][sl + 2]);
                    mma16816(acc[mt][nt], al[mt], bh[pr][sl], bh[pr][sl + 2]);
                }
        }
        __syncthreads();
    }
    CP_WAIT(0);

    // ------------------------------ epilogues ------------------------------
    const int g = lane >> 2, tq = lane & 3;

    if (MODE == 0 && sel < 2) {
        __nv_bfloat16* Chi = (sel == 0) ? g_Qhi : g_Khi;
        __nv_bfloat16* Clo = (sel == 0) ? g_Qlo : g_Klo;
        #pragma unroll
        for (int mt = 0; mt < 4; ++mt)
            #pragma unroll
            for (int nt = 0; nt < 4; ++nt) {
                const int cc = wn * 32 + nt * 8 + tq * 2;
                const float b0 = bias[n0 + cc], b1 = bias[n0 + cc + 1];
                #pragma unroll
                for (int h = 0; h < 2; ++h) {
                    const long row = m0 + wm * 64 + mt * 16 + g + h * 8;
                    __nv_bfloat16 h0, l0, h1, l1;
                    bsplit(acc[mt][nt][h * 2 + 0] + b0, h0, l0);
                    bsplit(acc[mt][nt][h * 2 + 1] + b1, h1, l1);
                    *(uint32_t*)(Chi + row * Hh + n0 + cc) = pack2(h0, h1);
                    *(uint32_t*)(Clo + row * Hh + n0 + cc) = pack2(l0, l1);
                }
            }
    } else if (MODE == 0) {
        // V: fp32 smem transpose, then coalesced [b][h][s] hi/lo store
        float* stf = (float*)smem;
        #pragma unroll
        for (int mt = 0; mt < 4; ++mt)
            #pragma unroll
            for (int nt = 0; nt < 4; ++nt) {
                const int cc = wn * 32 + nt * 8 + tq * 2;
                const float b0 = bias[n0 + cc], b1 = bias[n0 + cc + 1];
                #pragma unroll
                for (int h = 0; h < 2; ++h) {
                    const int rr = wm * 64 + mt * 16 + g + h * 8;
                    stf[rr * 129 + cc]     = acc[mt][nt][h * 2 + 0] + b0;
                    stf[rr * 129 + cc + 1] = acc[mt][nt][h * 2 + 1] + b1;
                }
            }
        __syncthreads();
        const int m = tid & 127, nb = tid >> 7;
        const long bq = m0 >> 11, s0 = m0 & 2047;
        for (int n2 = 0; n2 < 64; ++n2) {
            const int n = n2 * 2 + nb;
            const float v = stf[m * 129 + n];
            __nv_bfloat16 h, l;
            bsplit(v, h, l);
            const long off = bq * ((long)Hh * Ss) + (n0 + n) * (long)Ss + s0 + m;
            g_Vthi[off] = h;
            g_Vtlo[off] = l;
        }
    } else if (MODE == 1) {
        float* Sp = g_S + (long)b * Ss * Ss;
        #pragma unroll
        for (int mt = 0; mt < 4; ++mt)
            #pragma unroll
            for (int nt = 0; nt < 4; ++nt) {
                const int cc = wn * 32 + nt * 8 + tq * 2;
                const int mk0 = mask[(long)b * Ss + n0 + cc];
                const int mk1 = mask[(long)b * Ss + n0 + cc + 1];
                #pragma unroll
                for (int h = 0; h < 2; ++h) {
                    const long row = m0 + wm * 64 + mt * 16 + g + h * 8;
                    float2 o;
                    o.x = mk0 ? acc[mt][nt][h * 2 + 0] * 0.03125f : -1e9f;
                    o.y = mk1 ? acc[mt][nt][h * 2 + 1] * 0.03125f : -1e9f;
                    *(float2*)(Sp + row * Ss + n0 + cc) = o;
                }
            }
    } else {
        #pragma unroll
        for (int mt = 0; mt < 4; ++mt)
            #pragma unroll
            for (int h = 0; h < 2; ++h) {
                const long row = m0 + wm * 64 + mt * 16 + g + h * 8;
                const int qm = mask[(long)b * Ss + row];
                #pragma unroll
                for (int nt = 0; nt < 4; ++nt) {
                    const int cc = wn * 32 + nt * 8 + tq * 2;
                    float2 o;
                    o.x = qm ? acc[mt][nt][h * 2 + 0] : 0.0f;
                    o.y = qm ? acc[mt][nt][h * 2 + 1] : 0.0f;
                    *(float2*)(out + ((long)b * Ss + row) * Hh + n0 + cc) = o;
                }
            }
    }
}

// ---------------------------------------------------------------------------
// Row softmax (S=2048) reading fp32 g_S, writing bf16 hi/lo prob planes.
// ---------------------------------------------------------------------------
__device__ __forceinline__ float warp_max(float v) {
    #pragma unroll
    for (int o = 16; o > 0; o >>= 1) v = fmaxf(v, __shfl_xor_sync(0xffffffffu, v, o));
    return v;
}
__device__ __forceinline__ float warp_sum(float v) {
    #pragma unroll
    for (int o = 16; o > 0; o >>= 1) v += __shfl_xor_sync(0xffffffffu, v, o);
    return v;
}

__global__ __launch_bounds__(256)
void softmax_kernel() {
    const long row = blockIdx.x;
    const float* __restrict__ p = g_S + row * (long)Ss;
    const int tid = threadIdx.x, lane = tid & 31, wid = tid >> 5;

    float4 v0 = ((const float4*)p)[tid];
    float4 v1 = ((const float4*)p)[tid + 256];
    float x[8] = {v0.x, v0.y, v0.z, v0.w, v1.x, v1.y, v1.z, v1.w};

    __shared__ float sh[8];

    float mx = x[0];
    #pragma unroll
    for (int i = 1; i < 8; ++i) mx = fmaxf(mx, x[i]);
    mx = warp_max(mx);
    if (lane == 0) sh[wid] = mx;
    __syncthreads();
    if (tid < 32) {
        float t = (lane < 8) ? sh[lane] : -CUDART_INF_F;
        t = warp_max(t);
        if (lane == 0) sh[0] = t;
    }
    __syncthreads();
    const float bmax = sh[0];
    __syncthreads();

    float e[8], s = 0.f;
    #pragma unroll
    for (int i = 0; i < 8; ++i) { e[i] = __expf(x[i] - bmax); s += e[i]; }
    s = warp_sum(s);
    if (lane == 0) sh[wid] = s;
    __syncthreads();
    if (tid < 32) {
        float t = (lane < 8) ? sh[lane] : 0.f;
        t = warp_sum(t);
        if (lane == 0) sh[0] = t;
    }
    __syncthreads();
    const float inv = 1.0f / sh[0];

    __nv_bfloat16 h[8], l[8];
    #pragma unroll
    for (int i = 0; i < 8; ++i) bsplit(e[i] * inv, h[i], l[i]);

    __nv_bfloat16* Phi = g_Phi + row * (long)Ss;
    __nv_bfloat16* Plo = g_Plo + row * (long)Ss;
    *(uint2*)(Phi + 4 * tid)        = make_uint2(pack2(h[0], h[1]), pack2(h[2], h[3]));
    *(uint2*)(Phi + 1024 + 4 * tid) = make_uint2(pack2(h[4], h[5]), pack2(h[6], h[7]));
    *(uint2*)(Plo + 4 * tid)        = make_uint2(pack2(l[0], l[1]), pack2(l[2], l[3]));
    *(uint2*)(Plo + 1024 + 4 * tid) = make_uint2(pack2(l[4], l[5]), pack2(l[6], l[7]));
}

// ---------------------------------------------------------------------------
extern "C" void kernel_launch(void* const* d_in, const int* in_sizes, int n_in,
                              void* d_out, int out_size) {
    const float* X    = (const float*)d_in[0];
    const int*   mask = (const int*)  d_in[1];
    const float* Wq   = (const float*)d_in[2];
    const float* bq   = (const float*)d_in[3];
    const float* Wk   = (const float*)d_in[4];
    const float* bk   = (const float*)d_in[5];
    const float* Wv   = (const float*)d_in[6];
    const float* bv   = (const float*)d_in[7];
    float* out = (float*)d_out;

    static bool attr_done = false;
    if (!attr_done) {
        cudaFuncSetAttribute(mma_gemm<0>, cudaFuncAttributeMaxDynamicSharedMemorySize, SMEM_BYTES);
        cudaFuncSetAttribute(mma_gemm<1>, cudaFuncAttributeMaxDynamicSharedMemorySize, SMEM_BYTES);
        cudaFuncSetAttribute(mma_gemm<2>, cudaFuncAttributeMaxDynamicSharedMemorySize, SMEM_BYTES);
        attr_done = true;
    }

    void *pXhi, *pXlo, *pWhi, *pWlo;
    cudaGetSymbolAddress(&pXhi, g_Xhi);
    cudaGetSymbolAddress(&pXlo, g_Xlo);
    cudaGetSymbolAddress(&pWhi, g_Whi);
    cudaGetSymbolAddress(&pWlo, g_Wlo);

    dim3 blk(256);

    // Split X and the three weight matrices into bf16 hi/lo planes
    convert_split<<<(long)Bb * Ss * Hh / 1024, blk>>>(X, (__nv_bfloat16*)pXhi, (__nv_bfloat16*)pXlo);
    convert_split<<<(long)Hh * Hh / 1024, blk>>>(Wq, (__nv_bfloat16*)pWhi, (__nv_bfloat16*)pWlo);
    convert_split<<<(long)Hh * Hh / 1024, blk>>>(Wk, (__nv_bfloat16*)pWhi + (long)Hh * Hh,
                                                     (__nv_bfloat16*)pWlo + (long)Hh * Hh);
    convert_split<<<(long)Hh * Hh / 1024, blk>>>(Wv, (__nv_bfloat16*)pWhi + 2L * Hh * Hh,
                                                     (__nv_bfloat16*)pWlo + 2L * Hh * Hh);

    // QKV projections (V stored transposed)
    dim3 grid_qkv((Bb * Ss) / 128, Hh / 128, 1);
    mma_gemm<0><<<grid_qkv, blk, SMEM_BYTES>>>(bq, nullptr, nullptr, 0);
    mma_gemm<0><<<grid_qkv, blk, SMEM_BYTES>>>(bk, nullptr, nullptr, 1);
    mma_gemm<0><<<grid_qkv, blk, SMEM_BYTES>>>(bv, nullptr, nullptr, 2);

    // Scores
    dim3 grid_sc(Ss / 128, Ss / 128, Bb);
    mma_gemm<1><<<grid_sc, blk, SMEM_BYTES>>>(nullptr, mask, nullptr, 0);

    // Softmax -> prob hi/lo planes
    softmax_kernel<<<Bb * Ss, blk>>>();

    // P @ V^T with query-mask epilogue
    dim3 grid_pv(Ss / 128, Hh / 128, Bb);
    mma_gemm<2><<<grid_pv, blk, SMEM_BYTES>>>(nullptr, mask, out, 0);
}

// round 7
// speedup vs baseline: 1.0012x; 1.0000x over previous
#include <cuda_runtime.h>
#include <cuda_bf16.h>
#include <cstdint>
#include <math_constants.h>

static constexpr int Bb = 16;
static constexpr int Ss = 2048;
static constexpr int Hh = 1024;

// ---------------------------------------------------------------------------
// Scratch planes (device globals: allocation-free rule)
// ---------------------------------------------------------------------------
__device__ __nv_bfloat16 g_Xhi[(long)Bb * Ss * Hh];
__device__ __nv_bfloat16 g_Xlo[(long)Bb * Ss * Hh];
__device__ __nv_bfloat16 g_Whi[3L * Hh * Hh];
__device__ __nv_bfloat16 g_Wlo[3L * Hh * Hh];
__device__ __nv_bfloat16 g_Qhi[(long)Bb * Ss * Hh];
__device__ __nv_bfloat16 g_Qlo[(long)Bb * Ss * Hh];
__device__ __nv_bfloat16 g_Khi[(long)Bb * Ss * Hh];
__device__ __nv_bfloat16 g_Klo[(long)Bb * Ss * Hh];
__device__ __nv_bfloat16 g_Vthi[(long)Bb * Hh * Ss];   // transposed: [b][h][s]
__device__ __nv_bfloat16 g_Vtlo[(long)Bb * Hh * Ss];
__device__ float         g_S  [(long)Bb * Ss * Ss];    // fp32 scores
__device__ __nv_bfloat16 g_Phi[(long)Bb * Ss * Ss];    // probs hi/lo
__device__ __nv_bfloat16 g_Plo[(long)Bb * Ss * Ss];

// ---------------------------------------------------------------------------
// Helpers
// ---------------------------------------------------------------------------
__device__ __forceinline__ uint32_t smem_u32(const void* p) {
    uint32_t a;
    asm("{ .reg .u64 t; cvta.to.shared.u64 t, %1; cvt.u32.u64 %0, t; }" : "=r"(a) : "l"(p));
    return a;
}

#define CP_ASYNC16(dst, src) \
    asm volatile("cp.async.cg.shared.global [%0], [%1], 16;" \
        :: "r"(dst), "l"(__cvta_generic_to_global(src)) : "memory")
#define CP_COMMIT asm volatile("cp.async.commit_group;" ::: "memory")
#define CP_WAIT(N) asm volatile("cp.async.wait_group %0;" :: "n"(N) : "memory")

__device__ __forceinline__ void ldsm4(uint32_t addr, uint32_t* r) {
    asm volatile("ldmatrix.sync.aligned.m8n8.x4.shared.b16 {%0,%1,%2,%3}, [%4];"
        : "=r"(r[0]), "=r"(r[1]), "=r"(r[2]), "=r"(r[3]) : "r"(addr));
}

__device__ __forceinline__ void mma16816(float* c, const uint32_t* a,
                                         uint32_t b0, uint32_t b1) {
    asm volatile(
        "mma.sync.aligned.m16n8k16.row.col.f32.bf16.bf16.f32 "
        "{%0,%1,%2,%3},{%4,%5,%6,%7},{%8,%9},{%0,%1,%2,%3};"
        : "+f"(c[0]), "+f"(c[1]), "+f"(c[2]), "+f"(c[3])
        : "r"(a[0]), "r"(a[1]), "r"(a[2]), "r"(a[3]), "r"(b0), "r"(b1));
}

__device__ __forceinline__ void bsplit(float x, __nv_bfloat16& h, __nv_bfloat16& l) {
    h = __float2bfloat16_rn(x);
    l = __float2bfloat16_rn(x - __bfloat162float(h));
}
__device__ __forceinline__ uint32_t pack2(__nv_bfloat16 a, __nv_bfloat16 b) {
    __nv_bfloat162 t(a, b);
    return *(uint32_t*)&t;
}

// ---------------------------------------------------------------------------
// Convert: fp32 -> bf16 hi/lo planes
// ---------------------------------------------------------------------------
__global__ __launch_bounds__(256)
void convert_split(const float* __restrict__ in,
                   __nv_bfloat16* __restrict__ hi,
                   __nv_bfloat16* __restrict__ lo) {
    const long i = ((long)blockIdx.x * 256 + threadIdx.x) * 4;
    float4 v = *(const float4*)(in + i);
    __nv_bfloat16 h0, h1, h2, h3, l0, l1, l2, l3;
    bsplit(v.x, h0, l0); bsplit(v.y, h1, l1);
    bsplit(v.z, h2, l2); bsplit(v.w, h3, l3);
    *(uint2*)(hi + i) = make_uint2(pack2(h0, h1), pack2(h2, h3));
    *(uint2*)(lo + i) = make_uint2(pack2(l0, l1), pack2(l2, l3));
}

// ---------------------------------------------------------------------------
// Unified bf16x3 mma.sync GEMM: block 128x128, K-chunk 32, 3-stage cp.async.
// MODE 0: sel 0/1: Q/K = X@W^T + b -> hi/lo planes; sel 2: V (transposed store)
// MODE 1: g_S[b] = mask-fill((Q K^T)/32)  fp32
// MODE 2: out[b] = qmask * (P @ Vt^T)
// ---------------------------------------------------------------------------
static constexpr int PITCH = 80;                 // bytes/row (32 bf16 + pad)
static constexpr int PLANE = 128 * PITCH;        // 10240
static constexpr int STAGE = 4 * PLANE;          // Ahi Alo Bhi Blo = 40960
static constexpr int NSTG  = 3;
static constexpr int SMEM_BYTES = NSTG * STAGE;  // 122880

template<int MODE>
__global__ __launch_bounds__(256, 1)
void mma_gemm(const float* __restrict__ bias, const int* __restrict__ mask,
              float* __restrict__ out, int sel) {
    extern __shared__ char smem[];
    const uint32_t sbase = smem_u32(smem);
    const int tid = threadIdx.x, lane = tid & 31, wid = tid >> 5;
    const int wm = wid & 1, wn = wid >> 1;         // 2 x 4 warps
    const long m0 = (long)blockIdx.x * 128;
    const long n0 = (long)blockIdx.y * 128;
    const int  b  = blockIdx.z;

    const __nv_bfloat16 *Ahi, *Alo, *Bhi, *Blo;
    long ldA, ldB;
    constexpr int NC = (MODE == 2) ? 64 : 32;
    if (MODE == 0) {
        Ahi = g_Xhi; Alo = g_Xlo;
        Bhi = g_Whi + (long)sel * Hh * Hh; Blo = g_Wlo + (long)sel * Hh * Hh;
        ldA = Hh; ldB = Hh;
    } else if (MODE == 1) {
        Ahi = g_Qhi + (long)b * Ss * Hh; Alo = g_Qlo + (long)b * Ss * Hh;
        Bhi = g_Khi + (long)b * Ss * Hh; Blo = g_Klo + (long)b * Ss * Hh;
        ldA = Hh; ldB = Hh;
    } else {
        Ahi = g_Phi + (long)b * Ss * Ss; Alo = g_Plo + (long)b * Ss * Ss;
        Bhi = g_Vthi + (long)b * Hh * Ss; Blo = g_Vtlo + (long)b * Hh * Ss;
        ldA = Ss; ldB = Ss;
    }

    float acc[4][4][4] = {};

    auto issue = [&](int chunk) {
        const uint32_t st = sbase + (chunk % NSTG) * STAGE;
        const long k0 = (long)chunk * 32;
        #pragma unroll
        for (int i = 0; i < 8; ++i) {
            const int plane = i >> 1;                 // uniform per i
            const int q = ((i & 1) << 8) + tid;       // 0..511 within plane
            const int r = q >> 2, c4 = q & 3;
            const uint32_t dst = st + plane * PLANE + r * PITCH + c4 * 16;
            const __nv_bfloat16* src =
                (plane == 0) ? Ahi + (m0 + r) * ldA + k0 + c4 * 8 :
                (plane == 1) ? Alo + (m0 + r) * ldA + k0 + c4 * 8 :
                (plane == 2) ? Bhi + (n0 + r) * ldB + k0 + c4 * 8 :
                               Blo + (n0 + r) * ldB + k0 + c4 * 8;
            CP_ASYNC16(dst, src);
        }
    };

    issue(0); CP_COMMIT;
    issue(1); CP_COMMIT;

    for (int c = 0; c < NC; ++c) {
        if (c + 2 < NC) issue(c + 2);
        CP_COMMIT;
        CP_WAIT(2);
        __syncthreads();

        const uint32_t st = sbase + (c % NSTG) * STAGE;
        const int lr = lane & 15, lc = lane >> 4;
        #pragma unroll
        for (int ks = 0; ks < 2; ++ks) {
            uint32_t ah[4][4], al[4][4], bh[2][4], bl[2][4];
            #pragma unroll
            for (int mt = 0; mt < 4; ++mt) {
                const uint32_t off = (uint32_t)(wm * 64 + mt * 16 + lr) * PITCH + lc * 16 + ks * 32;
                ldsm4(st + off, ah[mt]);
                ldsm4(st + PLANE + off, al[mt]);
            }
            #pragma unroll
            for (int pr = 0; pr < 2; ++pr) {
                const uint32_t off = (uint32_t)(wn * 32 + pr * 16 + lr) * PITCH + lc * 16 + ks * 32;
                ldsm4(st + 2 * PLANE + off, bh[pr]);
                ldsm4(st + 3 * PLANE + off, bl[pr]);
            }
            #pragma unroll
            for (int mt = 0; mt < 4; ++mt)
                #pragma unroll
                for (int nt = 0; nt < 4; ++nt) {
                    const int pr = nt >> 1, sl = nt & 1;
                    mma16816(acc[mt][nt], ah[mt], bh[pr][sl], bh[pr][sl + 2]);
                    mma16816(acc[mt][nt], ah[mt], bl[pr][sl], bl[pr][sl + 2]);
                    mma16816(acc[mt][nt], al[mt], bh[pr][sl], bh[pr][sl + 2]);
                }
        }
        __syncthreads();
    }
    CP_WAIT(0);

    // ------------------------------ epilogues ------------------------------
    const int g = lane >> 2, tq = lane & 3;

    if (MODE == 0 && sel < 2) {
        __nv_bfloat16* Chi = (sel == 0) ? g_Qhi : g_Khi;
        __nv_bfloat16* Clo = (sel == 0) ? g_Qlo : g_Klo;
        #pragma unroll
        for (int mt = 0; mt < 4; ++mt)
            #pragma unroll
            for (int nt = 0; nt < 4; ++nt) {
                const int cc = wn * 32 + nt * 8 + tq * 2;
                const float b0 = bias[n0 + cc], b1 = bias[n0 + cc + 1];
                #pragma unroll
                for (int h = 0; h < 2; ++h) {
                    const long row = m0 + wm * 64 + mt * 16 + g + h * 8;
                    __nv_bfloat16 h0, l0, h1, l1;
                    bsplit(acc[mt][nt][h * 2 + 0] + b0, h0, l0);
                    bsplit(acc[mt][nt][h * 2 + 1] + b1, h1, l1);
                    *(uint32_t*)(Chi + row * Hh + n0 + cc) = pack2(h0, h1);
                    *(uint32_t*)(Clo + row * Hh + n0 + cc) = pack2(l0, l1);
                }
            }
    } else if (MODE == 0) {
        // V: fp32 smem transpose, then coalesced [b][h][s] hi/lo store
        float* stf = (float*)smem;
        #pragma unroll
        for (int mt = 0; mt < 4; ++mt)
            #pragma unroll
            for (int nt = 0; nt < 4; ++nt) {
                const int cc = wn * 32 + nt * 8 + tq * 2;
                const float b0 = bias[n0 + cc], b1 = bias[n0 + cc + 1];
                #pragma unroll
                for (int h = 0; h < 2; ++h) {
                    const int rr = wm * 64 + mt * 16 + g + h * 8;
                    stf[rr * 129 + cc]     = acc[mt][nt][h * 2 + 0] + b0;
                    stf[rr * 129 + cc + 1] = acc[mt][nt][h * 2 + 1] + b1;
                }
            }
        __syncthreads();
        const int m = tid & 127, nb = tid >> 7;
        const long bq = m0 >> 11, s0 = m0 & 2047;
        for (int n2 = 0; n2 < 64; ++n2) {
            const int n = n2 * 2 + nb;
            const float v = stf[m * 129 + n];
            __nv_bfloat16 h, l;
            bsplit(v, h, l);
            const long off = bq * ((long)Hh * Ss) + (n0 + n) * (long)Ss + s0 + m;
            g_Vthi[off] = h;
            g_Vtlo[off] = l;
        }
    } else if (MODE == 1) {
        float* Sp = g_S + (long)b * Ss * Ss;
        #pragma unroll
        for (int mt = 0; mt < 4; ++mt)
            #pragma unroll
            for (int nt = 0; nt < 4; ++nt) {
                const int cc = wn * 32 + nt * 8 + tq * 2;
                const int mk0 = mask[(long)b * Ss + n0 + cc];
                const int mk1 = mask[(long)b * Ss + n0 + cc + 1];
                #pragma unroll
                for (int h = 0; h < 2; ++h) {
                    const long row = m0 + wm * 64 + mt * 16 + g + h * 8;
                    float2 o;
                    o.x = mk0 ? acc[mt][nt][h * 2 + 0] * 0.03125f : -1e9f;
                    o.y = mk1 ? acc[mt][nt][h * 2 + 1] * 0.03125f : -1e9f;
                    *(float2*)(Sp + row * Ss + n0 + cc) = o;
                }
            }
    } else {
        #pragma unroll
        for (int mt = 0; mt < 4; ++mt)
            #pragma unroll
            for (int h = 0; h < 2; ++h) {
                const long row = m0 + wm * 64 + mt * 16 + g + h * 8;
                const int qm = mask[(long)b * Ss + row];
                #pragma unroll
                for (int nt = 0; nt < 4; ++nt) {
                    const int cc = wn * 32 + nt * 8 + tq * 2;
                    float2 o;
                    o.x = qm ? acc[mt][nt][h * 2 + 0] : 0.0f;
                    o.y = qm ? acc[mt][nt][h * 2 + 1] : 0.0f;
                    *(float2*)(out + ((long)b * Ss + row) * Hh + n0 + cc) = o;
                }
            }
    }
}

// ---------------------------------------------------------------------------
// Row softmax (S=2048) reading fp32 g_S, writing bf16 hi/lo prob planes.
// ---------------------------------------------------------------------------
__device__ __forceinline__ float warp_max(float v) {
    #pragma unroll
    for (int o = 16; o > 0; o >>= 1) v = fmaxf(v, __shfl_xor_sync(0xffffffffu, v, o));
    return v;
}
__device__ __forceinline__ float warp_sum(float v) {
    #pragma unroll
    for (int o = 16; o > 0; o >>= 1) v += __shfl_xor_sync(0xffffffffu, v, o);
    return v;
}

__global__ __launch_bounds__(256)
void softmax_kernel() {
    const long row = blockIdx.x;
    const float* __restrict__ p = g_S + row * (long)Ss;
    const int tid = threadIdx.x, lane = tid & 31, wid = tid >> 5;

    float4 v0 = ((const float4*)p)[tid];
    float4 v1 = ((const float4*)p)[tid + 256];
    float x[8] = {v0.x, v0.y, v0.z, v0.w, v1.x, v1.y, v1.z, v1.w};

    __shared__ float sh[8];

    float mx = x[0];
    #pragma unroll
    for (int i = 1; i < 8; ++i) mx = fmaxf(mx, x[i]);
    mx = warp_max(mx);
    if (lane == 0) sh[wid] = mx;
    __syncthreads();
    if (tid < 32) {
        float t = (lane < 8) ? sh[lane] : -CUDART_INF_F;
        t = warp_max(t);
        if (lane == 0) sh[0] = t;
    }
    __syncthreads();
    const float bmax = sh[0];
    __syncthreads();

    float e[8], s = 0.f;
    #pragma unroll
    for (int i = 0; i < 8; ++i) { e[i] = __expf(x[i] - bmax); s += e[i]; }
    s = warp_sum(s);
    if (lane == 0) sh[wid] = s;
    __syncthreads();
    if (tid < 32) {
        float t = (lane < 8) ? sh[lane] : 0.f;
        t = warp_sum(t);
        if (lane == 0) sh[0] = t;
    }
    __syncthreads();
    const float inv = 1.0f / sh[0];

    __nv_bfloat16 h[8], l[8];
    #pragma unroll
    for (int i = 0; i < 8; ++i) bsplit(e[i] * inv, h[i], l[i]);

    __nv_bfloat16* Phi = g_Phi + row * (long)Ss;
    __nv_bfloat16* Plo = g_Plo + row * (long)Ss;
    *(uint2*)(Phi + 4 * tid)        = make_uint2(pack2(h[0], h[1]), pack2(h[2], h[3]));
    *(uint2*)(Phi + 1024 + 4 * tid) = make_uint2(pack2(h[4], h[5]), pack2(h[6], h[7]));
    *(uint2*)(Plo + 4 * tid)        = make_uint2(pack2(l[0], l[1]), pack2(l[2], l[3]));
    *(uint2*)(Plo + 1024 + 4 * tid) = make_uint2(pack2(l[4], l[5]), pack2(l[6], l[7]));
}

// ---------------------------------------------------------------------------
extern "C" void kernel_launch(void* const* d_in, const int* in_sizes, int n_in,
                              void* d_out, int out_size) {
    const float* X    = (const float*)d_in[0];
    const int*   mask = (const int*)  d_in[1];
    const float* Wq   = (const float*)d_in[2];
    const float* bq   = (const float*)d_in[3];
    const float* Wk   = (const float*)d_in[4];
    const float* bk   = (const float*)d_in[5];
    const float* Wv   = (const float*)d_in[6];
    const float* bv   = (const float*)d_in[7];
    float* out = (float*)d_out;

    static bool attr_done = false;
    if (!attr_done) {
        cudaFuncSetAttribute(mma_gemm<0>, cudaFuncAttributeMaxDynamicSharedMemorySize, SMEM_BYTES);
        cudaFuncSetAttribute(mma_gemm<1>, cudaFuncAttributeMaxDynamicSharedMemorySize, SMEM_BYTES);
        cudaFuncSetAttribute(mma_gemm<2>, cudaFuncAttributeMaxDynamicSharedMemorySize, SMEM_BYTES);
        attr_done = true;
    }

    void *pXhi, *pXlo, *pWhi, *pWlo;
    cudaGetSymbolAddress(&pXhi, g_Xhi);
    cudaGetSymbolAddress(&pXlo, g_Xlo);
    cudaGetSymbolAddress(&pWhi, g_Whi);
    cudaGetSymbolAddress(&pWlo, g_Wlo);

    dim3 blk(256);

    // Split X and the three weight matrices into bf16 hi/lo planes
    convert_split<<<(long)Bb * Ss * Hh / 1024, blk>>>(X, (__nv_bfloat16*)pXhi, (__nv_bfloat16*)pXlo);
    convert_split<<<(long)Hh * Hh / 1024, blk>>>(Wq, (__nv_bfloat16*)pWhi, (__nv_bfloat16*)pWlo);
    convert_split<<<(long)Hh * Hh / 1024, blk>>>(Wk, (__nv_bfloat16*)pWhi + (long)Hh * Hh,
                                                     (__nv_bfloat16*)pWlo + (long)Hh * Hh);
    convert_split<<<(long)Hh * Hh / 1024, blk>>>(Wv, (__nv_bfloat16*)pWhi + 2L * Hh * Hh,
                                                     (__nv_bfloat16*)pWlo + 2L * Hh * Hh);

    // QKV projections (V stored transposed)
    dim3 grid_qkv((Bb * Ss) / 128, Hh / 128, 1);
    mma_gemm<0><<<grid_qkv, blk, SMEM_BYTES>>>(bq, nullptr, nullptr, 0);
    mma_gemm<0><<<grid_qkv, blk, SMEM_BYTES>>>(bk, nullptr, nullptr, 1);
    mma_gemm<0><<<grid_qkv, blk, SMEM_BYTES>>>(bv, nullptr, nullptr, 2);

    // Scores
    dim3 grid_sc(Ss / 128, Ss / 128, Bb);
    mma_gemm<1><<<grid_sc, blk, SMEM_BYTES>>>(nullptr, mask, nullptr, 0);

    // Softmax -> prob hi/lo planes
    softmax_kernel<<<Bb * Ss, blk>>>();

    // P @ V^T with query-mask epilogue
    dim3 grid_pv(Ss / 128, Hh / 128, Bb);
    mma_gemm<2><<<grid_pv, blk, SMEM_BYTES>>>(nullptr, mask, out, 0);
}

// round 8
// speedup vs baseline: 1.0017x; 1.0004x over previous
#include <cuda_runtime.h>
#include <cuda_bf16.h>
#include <cstdint>
#include <math_constants.h>

static constexpr int Bb = 16;
static constexpr int Ss = 2048;
static constexpr int Hh = 1024;

// ---------------------------------------------------------------------------
// Scratch planes (device globals: allocation-free rule)
// ---------------------------------------------------------------------------
__device__ __nv_bfloat16 g_Xhi[(long)Bb * Ss * Hh];
__device__ __nv_bfloat16 g_Xlo[(long)Bb * Ss * Hh];
__device__ __nv_bfloat16 g_Whi[3L * Hh * Hh];
__device__ __nv_bfloat16 g_Wlo[3L * Hh * Hh];
__device__ __nv_bfloat16 g_Qhi[(long)Bb * Ss * Hh];
__device__ __nv_bfloat16 g_Qlo[(long)Bb * Ss * Hh];
__device__ __nv_bfloat16 g_Khi[(long)Bb * Ss * Hh];
__device__ __nv_bfloat16 g_Klo[(long)Bb * Ss * Hh];
__device__ __nv_bfloat16 g_Vthi[(long)Bb * Hh * Ss];   // transposed: [b][h][s]
__device__ __nv_bfloat16 g_Vtlo[(long)Bb * Hh * Ss];
__device__ float         g_S  [(long)Bb * Ss * Ss];    // fp32 scores
__device__ __nv_bfloat16 g_Phi[(long)Bb * Ss * Ss];    // probs hi/lo
__device__ __nv_bfloat16 g_Plo[(long)Bb * Ss * Ss];

// ---------------------------------------------------------------------------
// Helpers
// ---------------------------------------------------------------------------
__device__ __forceinline__ uint32_t smem_u32(const void* p) {
    uint32_t a;
    asm("{ .reg .u64 t; cvta.to.shared.u64 t, %1; cvt.u32.u64 %0, t; }" : "=r"(a) : "l"(p));
    return a;
}

#define CP_ASYNC16(dst, src) \
    asm volatile("cp.async.cg.shared.global [%0], [%1], 16;" \
        :: "r"(dst), "l"(__cvta_generic_to_global(src)) : "memory")
#define CP_COMMIT asm volatile("cp.async.commit_group;" ::: "memory")
#define CP_WAIT(N) asm volatile("cp.async.wait_group %0;" :: "n"(N) : "memory")

__device__ __forceinline__ void ldsm4(uint32_t addr, uint32_t* r) {
    asm volatile("ldmatrix.sync.aligned.m8n8.x4.shared.b16 {%0,%1,%2,%3}, [%4];"
        : "=r"(r[0]), "=r"(r[1]), "=r"(r[2]), "=r"(r[3]) : "r"(addr));
}

__device__ __forceinline__ void mma16816(float* c, const uint32_t* a,
                                         uint32_t b0, uint32_t b1) {
    asm volatile(
        "mma.sync.aligned.m16n8k16.row.col.f32.bf16.bf16.f32 "
        "{%0,%1,%2,%3},{%4,%5,%6,%7},{%8,%9},{%0,%1,%2,%3};"
        : "+f"(c[0]), "+f"(c[1]), "+f"(c[2]), "+f"(c[3])
        : "r"(a[0]), "r"(a[1]), "r"(a[2]), "r"(a[3]), "r"(b0), "r"(b1));
}

__device__ __forceinline__ void bsplit(float x, __nv_bfloat16& h, __nv_bfloat16& l) {
    h = __float2bfloat16_rn(x);
    l = __float2bfloat16_rn(x - __bfloat162float(h));
}
__device__ __forceinline__ uint32_t pack2(__nv_bfloat16 a, __nv_bfloat16 b) {
    __nv_bfloat162 t(a, b);
    return *(uint32_t*)&t;
}

// ---------------------------------------------------------------------------
// Convert: fp32 -> bf16 hi/lo planes
// ---------------------------------------------------------------------------
__global__ __launch_bounds__(256)
void convert_split(const float* __restrict__ in,
                   __nv_bfloat16* __restrict__ hi,
                   __nv_bfloat16* __restrict__ lo) {
    const long i = ((long)blockIdx.x * 256 + threadIdx.x) * 4;
    float4 v = *(const float4*)(in + i);
    __nv_bfloat16 h0, h1, h2, h3, l0, l1, l2, l3;
    bsplit(v.x, h0, l0); bsplit(v.y, h1, l1);
    bsplit(v.z, h2, l2); bsplit(v.w, h3, l3);
    *(uint2*)(hi + i) = make_uint2(pack2(h0, h1), pack2(h2, h3));
    *(uint2*)(lo + i) = make_uint2(pack2(l0, l1), pack2(l2, l3));
}

// ---------------------------------------------------------------------------
// Unified bf16x3 mma.sync GEMM: block 128x128, K-chunk 32, 3-stage cp.async.
// MODE 0: sel 0/1: Q/K = X@W^T + b -> hi/lo planes; sel 2: V (transposed store)
// MODE 1: g_S[b] = mask-fill((Q K^T)/32)  fp32
// MODE 2: out[b] = qmask * (P @ Vt^T)
// ---------------------------------------------------------------------------
static constexpr int PITCH = 80;                 // bytes/row (32 bf16 + pad)
static constexpr int PLANE = 128 * PITCH;        // 10240
static constexpr int STAGE = 4 * PLANE;          // Ahi Alo Bhi Blo = 40960
static constexpr int NSTG  = 3;
static constexpr int SMEM_BYTES = NSTG * STAGE;  // 122880

template<int MODE>
__global__ __launch_bounds__(256, 1)
void mma_gemm(const float* __restrict__ bias, const int* __restrict__ mask,
              float* __restrict__ out, int sel) {
    extern __shared__ char smem[];
    const uint32_t sbase = smem_u32(smem);
    const int tid = threadIdx.x, lane = tid & 31, wid = tid >> 5;
    const int wm = wid & 1, wn = wid >> 1;         // 2 x 4 warps
    const long m0 = (long)blockIdx.x * 128;
    const long n0 = (long)blockIdx.y * 128;
    const int  b  = blockIdx.z;

    const __nv_bfloat16 *Ahi, *Alo, *Bhi, *Blo;
    long ldA, ldB;
    constexpr int NC = (MODE == 2) ? 64 : 32;
    if (MODE == 0) {
        Ahi = g_Xhi; Alo = g_Xlo;
        Bhi = g_Whi + (long)sel * Hh * Hh; Blo = g_Wlo + (long)sel * Hh * Hh;
        ldA = Hh; ldB = Hh;
    } else if (MODE == 1) {
        Ahi = g_Qhi + (long)b * Ss * Hh; Alo = g_Qlo + (long)b * Ss * Hh;
        Bhi = g_Khi + (long)b * Ss * Hh; Blo = g_Klo + (long)b * Ss * Hh;
        ldA = Hh; ldB = Hh;
    } else {
        Ahi = g_Phi + (long)b * Ss * Ss; Alo = g_Plo + (long)b * Ss * Ss;
        Bhi = g_Vthi + (long)b * Hh * Ss; Blo = g_Vtlo + (long)b * Hh * Ss;
        ldA = Ss; ldB = Ss;
    }

    float acc[4][4][4] = {};

    auto issue = [&](int chunk) {
        const uint32_t st = sbase + (chunk % NSTG) * STAGE;
        const long k0 = (long)chunk * 32;
        #pragma unroll
        for (int i = 0; i < 8; ++i) {
            const int plane = i >> 1;                 // uniform per i
            const int q = ((i & 1) << 8) + tid;       // 0..511 within plane
            const int r = q >> 2, c4 = q & 3;
            const uint32_t dst = st + plane * PLANE + r * PITCH + c4 * 16;
            const __nv_bfloat16* src =
                (plane == 0) ? Ahi + (m0 + r) * ldA + k0 + c4 * 8 :
                (plane == 1) ? Alo + (m0 + r) * ldA + k0 + c4 * 8 :
                (plane == 2) ? Bhi + (n0 + r) * ldB + k0 + c4 * 8 :
                               Blo + (n0 + r) * ldB + k0 + c4 * 8;
            CP_ASYNC16(dst, src);
        }
    };

    issue(0); CP_COMMIT;
    issue(1); CP_COMMIT;

    for (int c = 0; c < NC; ++c) {
        if (c + 2 < NC) issue(c + 2);
        CP_COMMIT;
        CP_WAIT(2);
        __syncthreads();

        const uint32_t st = sbase + (c % NSTG) * STAGE;
        const int lr = lane & 15, lc = lane >> 4;
        #pragma unroll
        for (int ks = 0; ks < 2; ++ks) {
            uint32_t ah[4][4], al[4][4], bh[2][4], bl[2][4];
            #pragma unroll
            for (int mt = 0; mt < 4; ++mt) {
                const uint32_t off = (uint32_t)(wm * 64 + mt * 16 + lr) * PITCH + lc * 16 + ks * 32;
                ldsm4(st + off, ah[mt]);
                ldsm4(st + PLANE + off, al[mt]);
            }
            #pragma unroll
            for (int pr = 0; pr < 2; ++pr) {
                const uint32_t off = (uint32_t)(wn * 32 + pr * 16 + lr) * PITCH + lc * 16 + ks * 32;
                ldsm4(st + 2 * PLANE + off, bh[pr]);
                ldsm4(st + 3 * PLANE + off, bl[pr]);
            }
            #pragma unroll
            for (int mt = 0; mt < 4; ++mt)
                #pragma unroll
                for (int nt = 0; nt < 4; ++nt) {
                    const int pr = nt >> 1, sl = nt & 1;
                    mma16816(acc[mt][nt], ah[mt], bh[pr][sl], bh[pr][sl + 2]);
                    mma16816(acc[mt][nt], ah[mt], bl[pr][sl], bl[pr][sl + 2]);
                    mma16816(acc[mt][nt], al[mt], bh[pr][sl], bh[pr][sl + 2]);
                }
        }
        __syncthreads();
    }
    CP_WAIT(0);

    // ------------------------------ epilogues ------------------------------
    const int g = lane >> 2, tq = lane & 3;

    if (MODE == 0 && sel < 2) {
        __nv_bfloat16* Chi = (sel == 0) ? g_Qhi : g_Khi;
        __nv_bfloat16* Clo = (sel == 0) ? g_Qlo : g_Klo;
        #pragma unroll
        for (int mt = 0; mt < 4; ++mt)
            #pragma unroll
            for (int nt = 0; nt < 4; ++nt) {
                const int cc = wn * 32 + nt * 8 + tq * 2;
                const float b0 = bias[n0 + cc], b1 = bias[n0 + cc + 1];
                #pragma unroll
                for (int h = 0; h < 2; ++h) {
                    const long row = m0 + wm * 64 + mt * 16 + g + h * 8;
                    __nv_bfloat16 h0, l0, h1, l1;
                    bsplit(acc[mt][nt][h * 2 + 0] + b0, h0, l0);
                    bsplit(acc[mt][nt][h * 2 + 1] + b1, h1, l1);
                    *(uint32_t*)(Chi + row * Hh + n0 + cc) = pack2(h0, h1);
                    *(uint32_t*)(Clo + row * Hh + n0 + cc) = pack2(l0, l1);
                }
            }
    } else if (MODE == 0) {
        // V: fp32 smem transpose, then coalesced [b][h][s] hi/lo store
        float* stf = (float*)smem;
        #pragma unroll
        for (int mt = 0; mt < 4; ++mt)
            #pragma unroll
            for (int nt = 0; nt < 4; ++nt) {
                const int cc = wn * 32 + nt * 8 + tq * 2;
                const float b0 = bias[n0 + cc], b1 = bias[n0 + cc + 1];
                #pragma unroll
                for (int h = 0; h < 2; ++h) {
                    const int rr = wm * 64 + mt * 16 + g + h * 8;
                    stf[rr * 129 + cc]     = acc[mt][nt][h * 2 + 0] + b0;
                    stf[rr * 129 + cc + 1] = acc[mt][nt][h * 2 + 1] + b1;
                }
            }
        __syncthreads();
        const int m = tid & 127, nb = tid >> 7;
        const long bq = m0 >> 11, s0 = m0 & 2047;
        for (int n2 = 0; n2 < 64; ++n2) {
            const int n = n2 * 2 + nb;
            const float v = stf[m * 129 + n];
            __nv_bfloat16 h, l;
            bsplit(v, h, l);
            const long off = bq * ((long)Hh * Ss) + (n0 + n) * (long)Ss + s0 + m;
            g_Vthi[off] = h;
            g_Vtlo[off] = l;
        }
    } else if (MODE == 1) {
        float* Sp = g_S + (long)b * Ss * Ss;
        #pragma unroll
        for (int mt = 0; mt < 4; ++mt)
            #pragma unroll
            for (int nt = 0; nt < 4; ++nt) {
                const int cc = wn * 32 + nt * 8 + tq * 2;
                const int mk0 = mask[(long)b * Ss + n0 + cc];
                const int mk1 = mask[(long)b * Ss + n0 + cc + 1];
                #pragma unroll
                for (int h = 0; h < 2; ++h) {
                    const long row = m0 + wm * 64 + mt * 16 + g + h * 8;
                    float2 o;
                    o.x = mk0 ? acc[mt][nt][h * 2 + 0] * 0.03125f : -1e9f;
                    o.y = mk1 ? acc[mt][nt][h * 2 + 1] * 0.03125f : -1e9f;
                    *(float2*)(Sp + row * Ss + n0 + cc) = o;
                }
            }
    } else {
        #pragma unroll
        for (int mt = 0; mt < 4; ++mt)
            #pragma unroll
            for (int h = 0; h < 2; ++h) {
                const long row = m0 + wm * 64 + mt * 16 + g + h * 8;
                const int qm = mask[(long)b * Ss + row];
                #pragma unroll
                for (int nt = 0; nt < 4; ++nt) {
                    const int cc = wn * 32 + nt * 8 + tq * 2;
                    float2 o;
                    o.x = qm ? acc[mt][nt][h * 2 + 0] : 0.0f;
                    o.y = qm ? acc[mt][nt][h * 2 + 1] : 0.0f;
                    *(float2*)(out + ((long)b * Ss + row) * Hh + n0 + cc) = o;
                }
            }
    }
}

// ---------------------------------------------------------------------------
// Row softmax (S=2048) reading fp32 g_S, writing bf16 hi/lo prob planes.
// ---------------------------------------------------------------------------
__device__ __forceinline__ float warp_max(float v) {
    #pragma unroll
    for (int o = 16; o > 0; o >>= 1) v = fmaxf(v, __shfl_xor_sync(0xffffffffu, v, o));
    return v;
}
__device__ __forceinline__ float warp_sum(float v) {
    #pragma unroll
    for (int o = 16; o > 0; o >>= 1) v += __shfl_xor_sync(0xffffffffu, v, o);
    return v;
}

__global__ __launch_bounds__(256)
void softmax_kernel() {
    const long row = blockIdx.x;
    const float* __restrict__ p = g_S + row * (long)Ss;
    const int tid = threadIdx.x, lane = tid & 31, wid = tid >> 5;

    float4 v0 = ((const float4*)p)[tid];
    float4 v1 = ((const float4*)p)[tid + 256];
    float x[8] = {v0.x, v0.y, v0.z, v0.w, v1.x, v1.y, v1.z, v1.w};

    __shared__ float sh[8];

    float mx = x[0];
    #pragma unroll
    for (int i = 1; i < 8; ++i) mx = fmaxf(mx, x[i]);
    mx = warp_max(mx);
    if (lane == 0) sh[wid] = mx;
    __syncthreads();
    if (tid < 32) {
        float t = (lane < 8) ? sh[lane] : -CUDART_INF_F;
        t = warp_max(t);
        if (lane == 0) sh[0] = t;
    }
    __syncthreads();
    const float bmax = sh[0];
    __syncthreads();

    float e[8], s = 0.f;
    #pragma unroll
    for (int i = 0; i < 8; ++i) { e[i] = __expf(x[i] - bmax); s += e[i]; }
    s = warp_sum(s);
    if (lane == 0) sh[wid] = s;
    __syncthreads();
    if (tid < 32) {
        float t = (lane < 8) ? sh[lane] : 0.f;
        t = warp_sum(t);
        if (lane == 0) sh[0] = t;
    }
    __syncthreads();
    const float inv = 1.0f / sh[0];

    __nv_bfloat16 h[8], l[8];
    #pragma unroll
    for (int i = 0; i < 8; ++i) bsplit(e[i] * inv, h[i], l[i]);

    __nv_bfloat16* Phi = g_Phi + row * (long)Ss;
    __nv_bfloat16* Plo = g_Plo + row * (long)Ss;
    *(uint2*)(Phi + 4 * tid)        = make_uint2(pack2(h[0], h[1]), pack2(h[2], h[3]));
    *(uint2*)(Phi + 1024 + 4 * tid) = make_uint2(pack2(h[4], h[5]), pack2(h[6], h[7]));
    *(uint2*)(Plo + 4 * tid)        = make_uint2(pack2(l[0], l[1]), pack2(l[2], l[3]));
    *(uint2*)(Plo + 1024 + 4 * tid) = make_uint2(pack2(l[4], l[5]), pack2(l[6], l[7]));
}

// ---------------------------------------------------------------------------
extern "C" void kernel_launch(void* const* d_in, const int* in_sizes, int n_in,
                              void* d_out, int out_size) {
    const float* X    = (const float*)d_in[0];
    const int*   mask = (const int*)  d_in[1];
    const float* Wq   = (const float*)d_in[2];
    const float* bq   = (const float*)d_in[3];
    const float* Wk   = (const float*)d_in[4];
    const float* bk   = (const float*)d_in[5];
    const float* Wv   = (const float*)d_in[6];
    const float* bv   = (const float*)d_in[7];
    float* out = (float*)d_out;

    static bool attr_done = false;
    if (!attr_done) {
        cudaFuncSetAttribute(mma_gemm<0>, cudaFuncAttributeMaxDynamicSharedMemorySize, SMEM_BYTES);
        cudaFuncSetAttribute(mma_gemm<1>, cudaFuncAttributeMaxDynamicSharedMemorySize, SMEM_BYTES);
        cudaFuncSetAttribute(mma_gemm<2>, cudaFuncAttributeMaxDynamicSharedMemorySize, SMEM_BYTES);
        attr_done = true;
    }

    void *pXhi, *pXlo, *pWhi, *pWlo;
    cudaGetSymbolAddress(&pXhi, g_Xhi);
    cudaGetSymbolAddress(&pXlo, g_Xlo);
    cudaGetSymbolAddress(&pWhi, g_Whi);
    cudaGetSymbolAddress(&pWlo, g_Wlo);

    dim3 blk(256);

    // Split X and the three weight matrices into bf16 hi/lo planes
    convert_split<<<(long)Bb * Ss * Hh / 1024, blk>>>(X, (__nv_bfloat16*)pXhi, (__nv_bfloat16*)pXlo);
    convert_split<<<(long)Hh * Hh / 1024, blk>>>(Wq, (__nv_bfloat16*)pWhi, (__nv_bfloat16*)pWlo);
    convert_split<<<(long)Hh * Hh / 1024, blk>>>(Wk, (__nv_bfloat16*)pWhi + (long)Hh * Hh,
                                                     (__nv_bfloat16*)pWlo + (long)Hh * Hh);
    convert_split<<<(long)Hh * Hh / 1024, blk>>>(Wv, (__nv_bfloat16*)pWhi + 2L * Hh * Hh,
                                                     (__nv_bfloat16*)pWlo + 2L * Hh * Hh);

    // QKV projections (V stored transposed)
    dim3 grid_qkv((Bb * Ss) / 128, Hh / 128, 1);
    mma_gemm<0><<<grid_qkv, blk, SMEM_BYTES>>>(bq, nullptr, nullptr, 0);
    mma_gemm<0><<<grid_qkv, blk, SMEM_BYTES>>>(bk, nullptr, nullptr, 1);
    mma_gemm<0><<<grid_qkv, blk, SMEM_BYTES>>>(bv, nullptr, nullptr, 2);

    // Scores
    dim3 grid_sc(Ss / 128, Ss / 128, Bb);
    mma_gemm<1><<<grid_sc, blk, SMEM_BYTES>>>(nullptr, mask, nullptr, 0);

    // Softmax -> prob hi/lo planes
    softmax_kernel<<<Bb * Ss, blk>>>();

    // P @ V^T with query-mask epilogue
    dim3 grid_pv(Ss / 128, Hh / 128, Bb);
    mma_gemm<2><<<grid_pv, blk, SMEM_BYTES>>>(nullptr, mask, out, 0);
}